// round 11
// baseline (speedup 1.0000x reference)
#include <cuda_runtime.h>
#include <cstdint>

#define BB 4
#define GG 8
#define NVOX 110592            /* 48*48*48 */
#define NELEM 331776           /* NVOX*3 */
#define NU4 (NELEM/4)          /* 82944 */
#define KTOP 800
#define APB (NELEM/256)        /* 1296 blocks per sample, kernel A */
#define BPB (NU4/256)          /* 324 blocks per sample, kernel B */

// ---------------- device scratch (static, zero-init, self-cleaning) ----------
__device__ unsigned g_u[BB*NELEM];
__device__ unsigned g_list[BB*NELEM];
__device__ unsigned g_hist1[BB][2048];
__device__ unsigned g_hist2[BB][2048];
__device__ float    g_pos_sum[BB];
__device__ float    g_reg_sum[BB];
__device__ float    g_topsum[BB];
__device__ float    g_neg[BB];
__device__ float    g_kcnt[BB];
__device__ unsigned g_npos[BB];
__device__ unsigned g_k2[BB];
__device__ unsigned g_listn[BB];
__device__ int      g_done[BB];
__device__ int      g_b1[BB];
__device__ unsigned g_arriveA[BB];
__device__ unsigned g_arriveB[BB];
__device__ unsigned g_arriveF;

// ---------------- helpers ----------------
__device__ __forceinline__ float softplus0(float x) {
    return fmaxf(x, 0.0f) + log1pf(expf(-fabsf(x)));
}
__device__ __forceinline__ float sl1(float x) {
    float ax = fabsf(x);
    return (ax < 1.0f) ? 0.5f * x * x : ax - 0.5f;
}
__device__ __forceinline__ unsigned ordmap(float f) {
    unsigned bb = __float_as_uint(f);
    return (bb & 0x80000000u) ? ~bb : (bb | 0x80000000u);
}
__device__ __forceinline__ float unord(unsigned u) {
    unsigned bb = (u & 0x80000000u) ? (u ^ 0x80000000u) : ~u;
    return __uint_as_float(bb);
}
__device__ __forceinline__ unsigned wscan_incl(unsigned v, int lane) {
#pragma unroll
    for (int o = 1; o < 32; o <<= 1) {
        unsigned t = __shfl_up_sync(0xffffffffu, v, o);
        if (lane >= o) v += t;
    }
    return v;
}
// block-wide inclusive scan over 256 threads (thread 0 = topmost chunk).
// s_w must have >= 16 entries; contains garbage afterwards.
__device__ __forceinline__ unsigned bscan(unsigned v, unsigned* s_w, int tid, int lane) {
    unsigned pre = wscan_incl(v, lane);
    if (lane == 31) s_w[tid >> 5] = pre;
    __syncthreads();
    if (tid < 32) {
        unsigned t = (tid < 8) ? s_w[tid] : 0u;
        unsigned p = wscan_incl(t, tid);
        if (tid < 8) s_w[tid + 8] = p - t;      // exclusive warp offset
    }
    __syncthreads();
    return pre + s_w[8 + (tid >> 5)];
}

// ================= kernel A: per-element main pass + parallel level-1 select =
// grid (APB, BB), 256 threads, one (voxel, anchor) element per thread
__global__ void __launch_bounds__(256) k_A(const float* __restrict__ pred,
                                           const float* __restrict__ tgt) {
    __shared__ float s_gxp[GG], s_gxm[GG], s_gyp[GG], s_gym[GG], s_gzp[GG], s_gzm[GG];
    __shared__ float s_gx[GG], s_gy[GG], s_gz[GG], s_gd[GG], s_d3[GG];
    __shared__ unsigned s_hist[2048];
    __shared__ unsigned s_w[16];
    __shared__ unsigned s_total;
    __shared__ int s_last;

    const int b    = blockIdx.y;
    const int tid  = threadIdx.x;
    const int lane = tid & 31;

    if (tid < GG) {
        const float* t = tgt + (b * GG + tid) * 4;
        float gx = t[0], gy = t[1], gz = t[2], gd = t[3];
        float r2 = 0.5f * gd;
        s_gx[tid] = gx; s_gy[tid] = gy; s_gz[tid] = gz; s_gd[tid] = gd;
        s_gxp[tid] = gx + r2; s_gxm[tid] = gx - r2;
        s_gyp[tid] = gy + r2; s_gym[tid] = gy - r2;
        s_gzp[tid] = gz + r2; s_gzm[tid] = gz - r2;
        s_d3[tid] = gd * gd * gd;
    }
    for (int i = tid; i < 2048; i += 256) s_hist[i] = 0u;
    __syncthreads();

    const int e   = blockIdx.x * 256 + tid;          // element = vox*3 + a
    const int vox = e / 3;
    const int a   = e - vox * 3;
    const int w = vox % 48; const int t2 = vox / 48;
    const int h = t2 % 48;  const int d = t2 / 48;
    const float cx = (float)(w * 4 + 2);
    const float cy = (float)(h * 4 + 2);
    const float cz = (float)(d * 4 + 2);

    const float r1 = 2.5f * (float)(1 << a);                         // anchor/2
    const float a3 = 125.0f * (float)(1 << (3 * a));                 // anchor^3
    const float ia = __uint_as_float(0x3E4CCCCDu - ((unsigned)a << 23)); // 0.2/2^a

    const float* p = pred + ((size_t)b * NELEM + (size_t)e) * 5;
    const float conf = p[0];

    float bi = -1.0f, bu = 1.0f;
    int bidx = 0;
#pragma unroll
    for (int g = 0; g < GG; g++) {
        float ix = fminf(cx + r1, s_gxp[g]) - fmaxf(cx - r1, s_gxm[g]); ix = fmaxf(ix, 0.0f);
        float iy = fminf(cy + r1, s_gyp[g]) - fmaxf(cy - r1, s_gym[g]); iy = fmaxf(iy, 0.0f);
        float iz = fminf(cz + r1, s_gzp[g]) - fmaxf(cz - r1, s_gzm[g]); iz = fmaxf(iz, 0.0f);
        float inter = ix * iy * iz;
        float un = a3 + s_d3[g] - inter + 1e-6f;
        if (inter * bu > bi * un) { bi = inter; bu = un; bidx = g; }
    }

    const bool pos = bi > 0.5f  * bu;
    const bool neg = bi < 0.02f * bu;
    unsigned u = 0u;
    if (neg) { u = ordmap(conf); atomicAdd(&s_hist[u >> 21], 1u); }
    g_u[(size_t)b * NELEM + e] = u;

    float lpos = 0.0f, lreg = 0.0f;
    unsigned lnp = 0;
    if (pos) {
        lnp = 1;
        lpos = fmaxf(conf, 0.0f) - conf + log1pf(expf(-fabsf(conf)));
        int g = bidx;
        float tx = (s_gx[g] - cx) * ia;
        float ty = (s_gy[g] - cy) * ia;
        float tz = (s_gz[g] - cz) * ia;
        float td = logf(s_gd[g] * ia);
        lreg = sl1(p[1] - tx) + sl1(p[2] - ty) + sl1(p[3] - tz) + sl1(p[4] - td);
    }
#pragma unroll
    for (int o = 16; o; o >>= 1) {
        lpos += __shfl_down_sync(0xffffffffu, lpos, o);
        lreg += __shfl_down_sync(0xffffffffu, lreg, o);
        lnp  += __shfl_down_sync(0xffffffffu, lnp, o);
    }
    if (lane == 0 && lnp) {
        atomicAdd(&g_pos_sum[b], lpos);
        atomicAdd(&g_reg_sum[b], lreg);
        atomicAdd(&g_npos[b], lnp);
    }
    __syncthreads();
    for (int i = tid; i < 2048; i += 256) {
        unsigned c = s_hist[i];
        if (c) atomicAdd(&g_hist1[b][i], c);
    }
    __threadfence();
    __syncthreads();
    if (tid == 0) s_last = (atomicAdd(&g_arriveA[b], 1u) == APB - 1);
    __syncthreads();
    if (!s_last) return;

    // ---- parallel level-1 selection: 8 bins per thread, descending ----
    __threadfence();   // acquire
    unsigned c8[8]; unsigned cnt = 0;
    const int base1 = 2047 - 8 * tid;
#pragma unroll
    for (int j = 0; j < 8; j++) { c8[j] = __ldcg(&g_hist1[b][base1 - j]); cnt += c8[j]; }
    unsigned pre = bscan(cnt, s_w, tid, lane);
    if (tid == 255) s_total = pre;
    __syncthreads();
    const unsigned total = s_total;
    if (total <= KTOP) {
        if (tid == 0) { g_done[b] = 1; g_kcnt[b] = (float)total; }
    } else {
        if (tid == 0) { g_done[b] = 0; g_kcnt[b] = (float)KTOP; }
        unsigned excl = pre - cnt;
        if (excl < KTOP && pre >= KTOP) {
            unsigned c = excl;
#pragma unroll
            for (int j = 0; j < 8; j++) {
                if (c + c8[j] >= KTOP) { g_b1[b] = base1 - j; g_k2[b] = KTOP - c; break; }
                c += c8[j];
            }
        }
    }
    __syncthreads();
    for (int i = tid; i < 2048; i += 256) g_hist1[b][i] = 0u;   // self-clean
    if (tid == 0) g_arriveA[b] = 0u;
}

// ================= kernel B: refine + hist2 + parallel tail + finalize =======
// grid (BPB, BB), 256 threads, one uint4 per thread
__global__ void __launch_bounds__(256) k_B(float* __restrict__ out) {
    __shared__ unsigned sh3[1024];
    __shared__ unsigned s_w[16];
    __shared__ float s_acc, s_c;
    __shared__ int s_last, s_fin, s_b2;
    __shared__ unsigned s_k3;

    const int b    = blockIdx.y;
    const int tid  = threadIdx.x;
    const int lane = tid & 31;
    const int done = g_done[b];
    const int b1   = g_b1[b];

    const uint4 v = ((const uint4*)g_u)[(size_t)b * NU4 + blockIdx.x * 256 + tid];
    unsigned e[4] = {v.x, v.y, v.z, v.w};
    float s = 0.0f;
#pragma unroll
    for (int q = 0; q < 4; q++) {
        unsigned u = e[q];
        if (!u) continue;
        if (done) {
            s += softplus0(unord(u));
        } else {
            int tb = (int)(u >> 21);
            if (tb > b1) s += softplus0(unord(u));
            else if (tb == b1) {
                unsigned idx = atomicAdd(&g_listn[b], 1u);
                g_list[(size_t)b * NELEM + idx] = u;
                atomicAdd(&g_hist2[b][(u >> 10) & 0x7FFu], 1u);
            }
        }
    }
#pragma unroll
    for (int o = 16; o; o >>= 1) s += __shfl_down_sync(0xffffffffu, s, o);
    if (lane == 0 && s != 0.0f) atomicAdd(&g_topsum[b], s);

    __threadfence();
    __syncthreads();
    if (tid == 0) s_last = (atomicAdd(&g_arriveB[b], 1u) == BPB - 1);
    __syncthreads();
    if (!s_last) return;

    // ---- per-sample parallel tail ----
    __threadfence();   // acquire
    const float kcnt = __ldcg(&g_kcnt[b]);

    if (done) {
        if (tid == 0) g_neg[b] = (kcnt > 0.0f) ? __ldcg(&g_topsum[b]) / kcnt : 0.0f;
        __syncthreads();
    } else {
        const unsigned k2 = __ldcg(&g_k2[b]);
        const unsigned n  = __ldcg(&g_listn[b]);
        const unsigned* lst = g_list + (size_t)b * NELEM;

        // level-2 selection: 8 bins per thread, descending, from g_hist2
        unsigned c8[8]; unsigned cnt = 0;
        const int base2 = 2047 - 8 * tid;
#pragma unroll
        for (int j = 0; j < 8; j++) { c8[j] = __ldcg(&g_hist2[b][base2 - j]); cnt += c8[j]; }
        unsigned pre = bscan(cnt, s_w, tid, lane);
        unsigned excl = pre - cnt;
        if (excl < k2 && pre >= k2) {
            unsigned c = excl;
#pragma unroll
            for (int j = 0; j < 8; j++) {
                if (c + c8[j] >= k2) { s_b2 = base2 - j; s_k3 = k2 - c; break; }
                c += c8[j];
            }
        }
        for (int q = tid; q < 1024; q += 256) sh3[q] = 0u;
        if (tid == 0) { s_acc = 0.0f; s_c = 0.0f; }
        __syncthreads();
        const int b2 = s_b2;
        const unsigned k3 = s_k3;

        // one parallel pass over the compacted list
        float s2 = 0.0f;
        for (unsigned q = tid; q < n; q += 256) {
            unsigned u = __ldcg(&lst[q]);
            int m = (int)((u >> 10) & 0x7FFu);
            if (m > b2) s2 += softplus0(unord(u));
            else if (m == b2) atomicAdd(&sh3[u & 0x3FFu], 1u);
        }
#pragma unroll
        for (int o = 16; o; o >>= 1) s2 += __shfl_down_sync(0xffffffffu, s2, o);
        if (lane == 0 && s2 != 0.0f) atomicAdd(&s_acc, s2);
        __syncthreads();

        // level-3 exact-value bins: 4 bins per thread, parallel softplus
        const unsigned pref = ((unsigned)b1 << 21) | ((unsigned)b2 << 10);
        unsigned c4[4]; unsigned cnt3 = 0; float ws = 0.0f;
        const int base3 = 1023 - 4 * tid;
#pragma unroll
        for (int j = 0; j < 4; j++) {
            unsigned cc = sh3[base3 - j];
            c4[j] = cc; cnt3 += cc;
            if (cc) ws += (float)cc * softplus0(unord(pref | (unsigned)(base3 - j)));
        }
        unsigned pre3 = bscan(cnt3, s_w, tid, lane);
        unsigned excl3 = pre3 - cnt3;
        float contrib = 0.0f;
        if (pre3 <= k3) contrib = ws;
        else if (excl3 < k3) {
            unsigned c = excl3;
#pragma unroll
            for (int j = 0; j < 4; j++) {
                if (!c4[j]) continue;
                float sp = softplus0(unord(pref | (unsigned)(base3 - j)));
                if (c + c4[j] >= k3) { contrib += (float)(k3 - c) * sp; break; }
                contrib += (float)c4[j] * sp;
                c += c4[j];
            }
        }
#pragma unroll
        for (int o = 16; o; o >>= 1) contrib += __shfl_down_sync(0xffffffffu, contrib, o);
        if (lane == 0 && contrib != 0.0f) atomicAdd(&s_c, contrib);
        __syncthreads();
        if (tid == 0) g_neg[b] = (__ldcg(&g_topsum[b]) + s_acc + s_c) / kcnt;
        // self-clean hist2
        for (int q = tid; q < 2048; q += 256) g_hist2[b][q] = 0u;
    }

    // per-sample cleanup, then cross-sample finalize
    if (tid == 0) { g_listn[b] = 0u; g_arriveB[b] = 0u; }
    __threadfence();
    __syncthreads();
    if (tid == 0) s_fin = (atomicAdd(&g_arriveF, 1u) == BB - 1);
    __syncthreads();
    if (s_fin && tid == 0) {
        __threadfence();   // acquire
        float cls = 0.0f, reg = 0.0f, npsum = 0.0f;
        for (int bb = 0; bb < BB; bb++) {
            float np = (float)__ldcg(&g_npos[bb]);
            float pl = (np > 0.0f) ? 5.0f * __ldcg(&g_pos_sum[bb]) / np : 0.0f;
            float rl = (np > 0.0f) ? __ldcg(&g_reg_sum[bb]) / (4.0f * np) : 0.0f;
            cls += pl + __ldcg(&g_neg[bb]);
            reg += rl;
            npsum += np;
            g_pos_sum[bb] = 0.0f; g_reg_sum[bb] = 0.0f;
            g_topsum[bb] = 0.0f;  g_npos[bb] = 0u;
        }
        g_arriveF = 0u;
        cls *= 0.25f;
        reg *= 0.25f;
        out[0] = cls + 0.5f * reg;
        out[1] = cls;
        out[2] = reg;
        out[3] = npsum;
    }
}

// ---------------- launcher ----------------
extern "C" void kernel_launch(void* const* d_in, const int* in_sizes, int n_in,
                              void* d_out, int out_size) {
    const float* pred = (const float*)d_in[0];   // (4,48,48,48,3,5)
    const float* tgt  = (const float*)d_in[1];   // (4,8,4)
    float* out = (float*)d_out;

    dim3 ga(APB, BB);          // 1296 x 4
    k_A<<<ga, 256>>>(pred, tgt);
    dim3 gb(BPB, BB);          // 324 x 4
    k_B<<<gb, 256>>>(out);
}

// round 12
// speedup vs baseline: 1.0143x; 1.0143x over previous
#include <cuda_runtime.h>
#include <cstdint>

#define BB 4
#define GG 8
#define NVOX 110592            /* 48*48*48 */
#define NELEM 331776           /* NVOX*3 */
#define NU4 (NELEM/4)          /* 82944 */
#define KTOP 800
#define APB (NELEM/256)        /* 1296 blocks per sample, kernel A */
#define BPB (NU4/256)          /* 324 blocks per sample, kernel B */

// ---------------- device scratch (static, zero-init, self-cleaning) ----------
__device__ unsigned g_u[BB*NELEM];
__device__ unsigned g_list[BB*NELEM];
__device__ unsigned g_hist1[BB][2048];
__device__ unsigned g_hist2[BB][2048];
__device__ float    g_pos_sum[BB];
__device__ float    g_reg_sum[BB];
__device__ float    g_topsum[BB];
__device__ float    g_neg[BB];
__device__ float    g_kcnt[BB];
__device__ unsigned g_npos[BB];
__device__ unsigned g_k2[BB];
__device__ unsigned g_listn[BB];
__device__ int      g_done[BB];
__device__ int      g_b1[BB];
__device__ unsigned g_arriveA[BB];
__device__ unsigned g_arriveB[BB];
__device__ unsigned g_arriveF;

// ---------------- helpers ----------------
__device__ __forceinline__ float softplus0(float x) {
    return fmaxf(x, 0.0f) + log1pf(expf(-fabsf(x)));
}
__device__ __forceinline__ float sl1(float x) {
    float ax = fabsf(x);
    return (ax < 1.0f) ? 0.5f * x * x : ax - 0.5f;
}
__device__ __forceinline__ unsigned ordmap(float f) {
    unsigned bb = __float_as_uint(f);
    return (bb & 0x80000000u) ? ~bb : (bb | 0x80000000u);
}
__device__ __forceinline__ float unord(unsigned u) {
    unsigned bb = (u & 0x80000000u) ? (u ^ 0x80000000u) : ~u;
    return __uint_as_float(bb);
}
__device__ __forceinline__ unsigned wscan_incl(unsigned v, int lane) {
#pragma unroll
    for (int o = 1; o < 32; o <<= 1) {
        unsigned t = __shfl_up_sync(0xffffffffu, v, o);
        if (lane >= o) v += t;
    }
    return v;
}
// block-wide inclusive scan over 256 threads (thread 0 = topmost chunk).
// s_w must have >= 16 entries; contains garbage afterwards.
__device__ __forceinline__ unsigned bscan(unsigned v, unsigned* s_w, int tid, int lane) {
    unsigned pre = wscan_incl(v, lane);
    if (lane == 31) s_w[tid >> 5] = pre;
    __syncthreads();
    if (tid < 32) {
        unsigned t = (tid < 8) ? s_w[tid] : 0u;
        unsigned p = wscan_incl(t, tid);
        if (tid < 8) s_w[tid + 8] = p - t;      // exclusive warp offset
    }
    __syncthreads();
    return pre + s_w[8 + (tid >> 5)];
}

// ================= kernel A: per-element main pass + parallel level-1 select =
// grid (APB, BB), 256 threads, one (voxel, anchor) element per thread
__global__ void __launch_bounds__(256) k_A(const float* __restrict__ pred,
                                           const float* __restrict__ tgt) {
    __shared__ float s_gxp[GG], s_gxm[GG], s_gyp[GG], s_gym[GG], s_gzp[GG], s_gzm[GG];
    __shared__ float s_gx[GG], s_gy[GG], s_gz[GG], s_gd[GG], s_d3[GG];
    __shared__ unsigned s_hist[2048];
    __shared__ unsigned s_w[16];
    __shared__ unsigned s_total;
    __shared__ int s_last;

    const int b    = blockIdx.y;
    const int tid  = threadIdx.x;
    const int lane = tid & 31;

    if (tid < GG) {
        const float* t = tgt + (b * GG + tid) * 4;
        float gx = t[0], gy = t[1], gz = t[2], gd = t[3];
        float r2 = 0.5f * gd;
        s_gx[tid] = gx; s_gy[tid] = gy; s_gz[tid] = gz; s_gd[tid] = gd;
        s_gxp[tid] = gx + r2; s_gxm[tid] = gx - r2;
        s_gyp[tid] = gy + r2; s_gym[tid] = gy - r2;
        s_gzp[tid] = gz + r2; s_gzm[tid] = gz - r2;
        s_d3[tid] = gd * gd * gd;
    }
    for (int i = tid; i < 2048; i += 256) s_hist[i] = 0u;
    __syncthreads();

    const int e   = blockIdx.x * 256 + tid;          // element = vox*3 + a
    const int vox = e / 3;
    const int a   = e - vox * 3;
    const int w = vox % 48; const int t2 = vox / 48;
    const int h = t2 % 48;  const int d = t2 / 48;
    const float cx = (float)(w * 4 + 2);
    const float cy = (float)(h * 4 + 2);
    const float cz = (float)(d * 4 + 2);

    const float r1 = 2.5f * (float)(1 << a);                         // anchor/2
    const float a3 = 125.0f * (float)(1 << (3 * a));                 // anchor^3
    const float ia = __uint_as_float(0x3E4CCCCDu - ((unsigned)a << 23)); // 0.2/2^a

    const float* p = pred + ((size_t)b * NELEM + (size_t)e) * 5;
    const float conf = p[0];

    float bi = -1.0f, bu = 1.0f;
    int bidx = 0;
#pragma unroll
    for (int g = 0; g < GG; g++) {
        float ix = fminf(cx + r1, s_gxp[g]) - fmaxf(cx - r1, s_gxm[g]); ix = fmaxf(ix, 0.0f);
        float iy = fminf(cy + r1, s_gyp[g]) - fmaxf(cy - r1, s_gym[g]); iy = fmaxf(iy, 0.0f);
        float iz = fminf(cz + r1, s_gzp[g]) - fmaxf(cz - r1, s_gzm[g]); iz = fmaxf(iz, 0.0f);
        float inter = ix * iy * iz;
        float un = a3 + s_d3[g] - inter + 1e-6f;
        if (inter * bu > bi * un) { bi = inter; bu = un; bidx = g; }
    }

    const bool pos = bi > 0.5f  * bu;
    const bool neg = bi < 0.02f * bu;
    unsigned u = 0u;
    if (neg) { u = ordmap(conf); atomicAdd(&s_hist[u >> 21], 1u); }
    g_u[(size_t)b * NELEM + e] = u;

    float lpos = 0.0f, lreg = 0.0f;
    unsigned lnp = 0;
    if (pos) {
        lnp = 1;
        lpos = fmaxf(conf, 0.0f) - conf + log1pf(expf(-fabsf(conf)));
        int g = bidx;
        float tx = (s_gx[g] - cx) * ia;
        float ty = (s_gy[g] - cy) * ia;
        float tz = (s_gz[g] - cz) * ia;
        float td = logf(s_gd[g] * ia);
        lreg = sl1(p[1] - tx) + sl1(p[2] - ty) + sl1(p[3] - tz) + sl1(p[4] - td);
    }
#pragma unroll
    for (int o = 16; o; o >>= 1) {
        lpos += __shfl_down_sync(0xffffffffu, lpos, o);
        lreg += __shfl_down_sync(0xffffffffu, lreg, o);
        lnp  += __shfl_down_sync(0xffffffffu, lnp, o);
    }
    if (lane == 0 && lnp) {
        atomicAdd(&g_pos_sum[b], lpos);
        atomicAdd(&g_reg_sum[b], lreg);
        atomicAdd(&g_npos[b], lnp);
    }
    __syncthreads();
    for (int i = tid; i < 2048; i += 256) {
        unsigned c = s_hist[i];
        if (c) atomicAdd(&g_hist1[b][i], c);
    }
    __threadfence();
    __syncthreads();
    if (tid == 0) s_last = (atomicAdd(&g_arriveA[b], 1u) == APB - 1);
    __syncthreads();
    if (!s_last) return;

    // ---- parallel level-1 selection: 8 bins per thread, descending ----
    __threadfence();   // acquire
    unsigned c8[8]; unsigned cnt = 0;
    const int base1 = 2047 - 8 * tid;
#pragma unroll
    for (int j = 0; j < 8; j++) { c8[j] = __ldcg(&g_hist1[b][base1 - j]); cnt += c8[j]; }
    unsigned pre = bscan(cnt, s_w, tid, lane);
    if (tid == 255) s_total = pre;
    __syncthreads();
    const unsigned total = s_total;
    if (total <= KTOP) {
        if (tid == 0) { g_done[b] = 1; g_kcnt[b] = (float)total; }
    } else {
        if (tid == 0) { g_done[b] = 0; g_kcnt[b] = (float)KTOP; }
        unsigned excl = pre - cnt;
        if (excl < KTOP && pre >= KTOP) {
            unsigned c = excl;
#pragma unroll
            for (int j = 0; j < 8; j++) {
                if (c + c8[j] >= KTOP) { g_b1[b] = base1 - j; g_k2[b] = KTOP - c; break; }
                c += c8[j];
            }
        }
    }
    __syncthreads();
    for (int i = tid; i < 2048; i += 256) g_hist1[b][i] = 0u;   // self-clean
    if (tid == 0) g_arriveA[b] = 0u;
}

// ================= kernel B: refine + hist2 + parallel tail + finalize =======
// grid (BPB, BB), 256 threads, one uint4 per thread
__global__ void __launch_bounds__(256) k_B(float* __restrict__ out) {
    __shared__ unsigned sh3[1024];
    __shared__ unsigned s_w[16];
    __shared__ float s_acc, s_c;
    __shared__ int s_last, s_fin, s_b2;
    __shared__ unsigned s_k3;

    const int b    = blockIdx.y;
    const int tid  = threadIdx.x;
    const int lane = tid & 31;
    const int done = g_done[b];
    const int b1   = g_b1[b];

    const uint4 v = ((const uint4*)g_u)[(size_t)b * NU4 + blockIdx.x * 256 + tid];
    unsigned e[4] = {v.x, v.y, v.z, v.w};
    float s = 0.0f;
#pragma unroll
    for (int q = 0; q < 4; q++) {
        unsigned u = e[q];
        if (!u) continue;
        if (done) {
            s += softplus0(unord(u));
        } else {
            int tb = (int)(u >> 21);
            if (tb > b1) s += softplus0(unord(u));
            else if (tb == b1) {
                unsigned idx = atomicAdd(&g_listn[b], 1u);
                g_list[(size_t)b * NELEM + idx] = u;
                atomicAdd(&g_hist2[b][(u >> 10) & 0x7FFu], 1u);
            }
        }
    }
#pragma unroll
    for (int o = 16; o; o >>= 1) s += __shfl_down_sync(0xffffffffu, s, o);
    if (lane == 0 && s != 0.0f) atomicAdd(&g_topsum[b], s);

    __threadfence();
    __syncthreads();
    if (tid == 0) s_last = (atomicAdd(&g_arriveB[b], 1u) == BPB - 1);
    __syncthreads();
    if (!s_last) return;

    // ---- per-sample parallel tail ----
    __threadfence();   // acquire
    const float kcnt = __ldcg(&g_kcnt[b]);

    if (done) {
        if (tid == 0) g_neg[b] = (kcnt > 0.0f) ? __ldcg(&g_topsum[b]) / kcnt : 0.0f;
        __syncthreads();
    } else {
        const unsigned k2 = __ldcg(&g_k2[b]);
        const unsigned n  = __ldcg(&g_listn[b]);
        const unsigned* lst = g_list + (size_t)b * NELEM;

        // level-2 selection: 8 bins per thread, descending, from g_hist2
        unsigned c8[8]; unsigned cnt = 0;
        const int base2 = 2047 - 8 * tid;
#pragma unroll
        for (int j = 0; j < 8; j++) { c8[j] = __ldcg(&g_hist2[b][base2 - j]); cnt += c8[j]; }
        unsigned pre = bscan(cnt, s_w, tid, lane);
        unsigned excl = pre - cnt;
        if (excl < k2 && pre >= k2) {
            unsigned c = excl;
#pragma unroll
            for (int j = 0; j < 8; j++) {
                if (c + c8[j] >= k2) { s_b2 = base2 - j; s_k3 = k2 - c; break; }
                c += c8[j];
            }
        }
        for (int q = tid; q < 1024; q += 256) sh3[q] = 0u;
        if (tid == 0) { s_acc = 0.0f; s_c = 0.0f; }
        __syncthreads();
        const int b2 = s_b2;
        const unsigned k3 = s_k3;

        // one parallel pass over the compacted list
        float s2 = 0.0f;
        for (unsigned q = tid; q < n; q += 256) {
            unsigned u = __ldcg(&lst[q]);
            int m = (int)((u >> 10) & 0x7FFu);
            if (m > b2) s2 += softplus0(unord(u));
            else if (m == b2) atomicAdd(&sh3[u & 0x3FFu], 1u);
        }
#pragma unroll
        for (int o = 16; o; o >>= 1) s2 += __shfl_down_sync(0xffffffffu, s2, o);
        if (lane == 0 && s2 != 0.0f) atomicAdd(&s_acc, s2);
        __syncthreads();

        // level-3 exact-value bins: 4 bins per thread, parallel softplus
        const unsigned pref = ((unsigned)b1 << 21) | ((unsigned)b2 << 10);
        unsigned c4[4]; unsigned cnt3 = 0; float ws = 0.0f;
        const int base3 = 1023 - 4 * tid;
#pragma unroll
        for (int j = 0; j < 4; j++) {
            unsigned cc = sh3[base3 - j];
            c4[j] = cc; cnt3 += cc;
            if (cc) ws += (float)cc * softplus0(unord(pref | (unsigned)(base3 - j)));
        }
        unsigned pre3 = bscan(cnt3, s_w, tid, lane);
        unsigned excl3 = pre3 - cnt3;
        float contrib = 0.0f;
        if (pre3 <= k3) contrib = ws;
        else if (excl3 < k3) {
            unsigned c = excl3;
#pragma unroll
            for (int j = 0; j < 4; j++) {
                if (!c4[j]) continue;
                float sp = softplus0(unord(pref | (unsigned)(base3 - j)));
                if (c + c4[j] >= k3) { contrib += (float)(k3 - c) * sp; break; }
                contrib += (float)c4[j] * sp;
                c += c4[j];
            }
        }
#pragma unroll
        for (int o = 16; o; o >>= 1) contrib += __shfl_down_sync(0xffffffffu, contrib, o);
        if (lane == 0 && contrib != 0.0f) atomicAdd(&s_c, contrib);
        __syncthreads();
        if (tid == 0) g_neg[b] = (__ldcg(&g_topsum[b]) + s_acc + s_c) / kcnt;
        // self-clean hist2
        for (int q = tid; q < 2048; q += 256) g_hist2[b][q] = 0u;
    }

    // per-sample cleanup, then cross-sample finalize
    if (tid == 0) { g_listn[b] = 0u; g_arriveB[b] = 0u; }
    __threadfence();
    __syncthreads();
    if (tid == 0) s_fin = (atomicAdd(&g_arriveF, 1u) == BB - 1);
    __syncthreads();
    if (s_fin && tid == 0) {
        __threadfence();   // acquire
        float cls = 0.0f, reg = 0.0f, npsum = 0.0f;
        for (int bb = 0; bb < BB; bb++) {
            float np = (float)__ldcg(&g_npos[bb]);
            float pl = (np > 0.0f) ? 5.0f * __ldcg(&g_pos_sum[bb]) / np : 0.0f;
            float rl = (np > 0.0f) ? __ldcg(&g_reg_sum[bb]) / (4.0f * np) : 0.0f;
            cls += pl + __ldcg(&g_neg[bb]);
            reg += rl;
            npsum += np;
            g_pos_sum[bb] = 0.0f; g_reg_sum[bb] = 0.0f;
            g_topsum[bb] = 0.0f;  g_npos[bb] = 0u;
        }
        g_arriveF = 0u;
        cls *= 0.25f;
        reg *= 0.25f;
        out[0] = cls + 0.5f * reg;
        out[1] = cls;
        out[2] = reg;
        out[3] = npsum;
    }
}

// ---------------- launcher ----------------
extern "C" void kernel_launch(void* const* d_in, const int* in_sizes, int n_in,
                              void* d_out, int out_size) {
    const float* pred = (const float*)d_in[0];   // (4,48,48,48,3,5)
    const float* tgt  = (const float*)d_in[1];   // (4,8,4)
    float* out = (float*)d_out;

    dim3 ga(APB, BB);          // 1296 x 4
    k_A<<<ga, 256>>>(pred, tgt);
    dim3 gb(BPB, BB);          // 324 x 4
    k_B<<<gb, 256>>>(out);
}

// round 13
// speedup vs baseline: 1.0555x; 1.0406x over previous
#include <cuda_runtime.h>
#include <cstdint>

#define BB 4
#define GG 8
#define NVOX 110592            /* 48*48*48 */
#define NELEM 331776           /* NVOX*3 */
#define NU4 (NELEM/4)          /* 82944 */
#define KTOP 800
#define APB (NELEM/256)        /* 1296 blocks per sample, kernel A */
#define BPB (NU4/256)          /* 324 blocks per sample, kernel B */

// ---------------- device scratch (static, zero-init, self-cleaning) ----------
__device__ unsigned g_u[BB*NELEM];
__device__ unsigned g_list[BB*NELEM];
__device__ unsigned g_hist1[BB][2048];
__device__ unsigned g_hist2[BB][2048];
__device__ float    g_pos_sum[BB];
__device__ float    g_reg_sum[BB];
__device__ float    g_topsum[BB];
__device__ float    g_neg[BB];
__device__ float    g_kcnt[BB];
__device__ unsigned g_npos[BB];
__device__ unsigned g_k2[BB];
__device__ unsigned g_listn[BB];
__device__ int      g_done[BB];
__device__ int      g_b1[BB];
__device__ unsigned g_arriveA[BB];
__device__ unsigned g_arriveB[BB];
__device__ unsigned g_arriveF;

// ---------------- helpers ----------------
__device__ __forceinline__ void fence_rel() {
    asm volatile("fence.release.gpu;" ::: "memory");
}
__device__ __forceinline__ void fence_acq() {
    asm volatile("fence.acquire.gpu;" ::: "memory");
}
__device__ __forceinline__ float softplus0(float x) {
    return fmaxf(x, 0.0f) + log1pf(expf(-fabsf(x)));
}
__device__ __forceinline__ float sl1(float x) {
    float ax = fabsf(x);
    return (ax < 1.0f) ? 0.5f * x * x : ax - 0.5f;
}
__device__ __forceinline__ unsigned ordmap(float f) {
    unsigned bb = __float_as_uint(f);
    return (bb & 0x80000000u) ? ~bb : (bb | 0x80000000u);
}
__device__ __forceinline__ float unord(unsigned u) {
    unsigned bb = (u & 0x80000000u) ? (u ^ 0x80000000u) : ~u;
    return __uint_as_float(bb);
}
__device__ __forceinline__ unsigned wscan_incl(unsigned v, int lane) {
#pragma unroll
    for (int o = 1; o < 32; o <<= 1) {
        unsigned t = __shfl_up_sync(0xffffffffu, v, o);
        if (lane >= o) v += t;
    }
    return v;
}
// block-wide inclusive scan over 256 threads (thread 0 = topmost chunk).
__device__ __forceinline__ unsigned bscan(unsigned v, unsigned* s_w, int tid, int lane) {
    unsigned pre = wscan_incl(v, lane);
    if (lane == 31) s_w[tid >> 5] = pre;
    __syncthreads();
    if (tid < 32) {
        unsigned t = (tid < 8) ? s_w[tid] : 0u;
        unsigned p = wscan_incl(t, tid);
        if (tid < 8) s_w[tid + 8] = p - t;      // exclusive warp offset
    }
    __syncthreads();
    return pre + s_w[8 + (tid >> 5)];
}

// ================= kernel A: per-element main pass + parallel level-1 select =
// grid (APB, BB), 256 threads, one (voxel, anchor) element per thread
__global__ void __launch_bounds__(256) k_A(const float* __restrict__ pred,
                                           const float* __restrict__ tgt) {
    __shared__ float s_gxp[GG], s_gxm[GG], s_gyp[GG], s_gym[GG], s_gzp[GG], s_gzm[GG];
    __shared__ float s_gx[GG], s_gy[GG], s_gz[GG], s_gd[GG], s_d3[GG];
    __shared__ unsigned s_hist[2048];
    __shared__ unsigned s_w[16];
    __shared__ unsigned s_total;
    __shared__ int s_last;

    const int b    = blockIdx.y;
    const int tid  = threadIdx.x;
    const int lane = tid & 31;

    if (tid < GG) {
        const float* t = tgt + (b * GG + tid) * 4;
        float gx = t[0], gy = t[1], gz = t[2], gd = t[3];
        float r2 = 0.5f * gd;
        s_gx[tid] = gx; s_gy[tid] = gy; s_gz[tid] = gz; s_gd[tid] = gd;
        s_gxp[tid] = gx + r2; s_gxm[tid] = gx - r2;
        s_gyp[tid] = gy + r2; s_gym[tid] = gy - r2;
        s_gzp[tid] = gz + r2; s_gzm[tid] = gz - r2;
        s_d3[tid] = gd * gd * gd;
    }
    for (int i = tid; i < 2048; i += 256) s_hist[i] = 0u;
    __syncthreads();

    const int e   = blockIdx.x * 256 + tid;          // element = vox*3 + a
    const int vox = e / 3;
    const int a   = e - vox * 3;
    const int w = vox % 48; const int t2 = vox / 48;
    const int h = t2 % 48;  const int d = t2 / 48;
    const float cx = (float)(w * 4 + 2);
    const float cy = (float)(h * 4 + 2);
    const float cz = (float)(d * 4 + 2);

    const float r1 = 2.5f * (float)(1 << a);                         // anchor/2
    const float a3 = 125.0f * (float)(1 << (3 * a));                 // anchor^3
    const float ia = __uint_as_float(0x3E4CCCCDu - ((unsigned)a << 23)); // 0.2/2^a

    const float* p = pred + ((size_t)b * NELEM + (size_t)e) * 5;
    const float conf = p[0];

    float bi = -1.0f, bu = 1.0f;
    int bidx = 0;
#pragma unroll
    for (int g = 0; g < GG; g++) {
        float ix = fminf(cx + r1, s_gxp[g]) - fmaxf(cx - r1, s_gxm[g]); ix = fmaxf(ix, 0.0f);
        float iy = fminf(cy + r1, s_gyp[g]) - fmaxf(cy - r1, s_gym[g]); iy = fmaxf(iy, 0.0f);
        float iz = fminf(cz + r1, s_gzp[g]) - fmaxf(cz - r1, s_gzm[g]); iz = fmaxf(iz, 0.0f);
        float inter = ix * iy * iz;
        float un = a3 + s_d3[g] - inter + 1e-6f;
        if (inter * bu > bi * un) { bi = inter; bu = un; bidx = g; }
    }

    const bool pos = bi > 0.5f  * bu;
    const bool neg = bi < 0.02f * bu;
    unsigned u = 0u;
    if (neg) { u = ordmap(conf); atomicAdd(&s_hist[u >> 21], 1u); }
    g_u[(size_t)b * NELEM + e] = u;

    float lpos = 0.0f, lreg = 0.0f;
    unsigned lnp = 0;
    if (pos) {
        lnp = 1;
        lpos = fmaxf(conf, 0.0f) - conf + log1pf(expf(-fabsf(conf)));
        int g = bidx;
        float tx = (s_gx[g] - cx) * ia;
        float ty = (s_gy[g] - cy) * ia;
        float tz = (s_gz[g] - cz) * ia;
        float td = logf(s_gd[g] * ia);
        lreg = sl1(p[1] - tx) + sl1(p[2] - ty) + sl1(p[3] - tz) + sl1(p[4] - td);
    }
#pragma unroll
    for (int o = 16; o; o >>= 1) {
        lpos += __shfl_down_sync(0xffffffffu, lpos, o);
        lreg += __shfl_down_sync(0xffffffffu, lreg, o);
        lnp  += __shfl_down_sync(0xffffffffu, lnp, o);
    }
    if (lane == 0 && lnp) {
        atomicAdd(&g_pos_sum[b], lpos);
        atomicAdd(&g_reg_sum[b], lreg);
        atomicAdd(&g_npos[b], lnp);
    }
    __syncthreads();
    for (int i = tid; i < 2048; i += 256) {
        unsigned c = s_hist[i];
        if (c) atomicAdd(&g_hist1[b][i], c);
    }
    // release: syncthreads gives block-wide HB into thread 0; thread 0 publishes
    __syncthreads();
    if (tid == 0) {
        fence_rel();
        s_last = (atomicAdd(&g_arriveA[b], 1u) == APB - 1);
    }
    __syncthreads();
    if (!s_last) return;

    // acquire (thread 0) + syncthreads makes all block reads ordered
    if (tid == 0) fence_acq();
    __syncthreads();

    // ---- parallel level-1 selection: 8 bins per thread, descending ----
    unsigned c8[8]; unsigned cnt = 0;
    const int base1 = 2047 - 8 * tid;
#pragma unroll
    for (int j = 0; j < 8; j++) { c8[j] = __ldcg(&g_hist1[b][base1 - j]); cnt += c8[j]; }
    unsigned pre = bscan(cnt, s_w, tid, lane);
    if (tid == 255) s_total = pre;
    __syncthreads();
    const unsigned total = s_total;
    if (total <= KTOP) {
        if (tid == 0) { g_done[b] = 1; g_kcnt[b] = (float)total; }
    } else {
        if (tid == 0) { g_done[b] = 0; g_kcnt[b] = (float)KTOP; }
        unsigned excl = pre - cnt;
        if (excl < KTOP && pre >= KTOP) {
            unsigned c = excl;
#pragma unroll
            for (int j = 0; j < 8; j++) {
                if (c + c8[j] >= KTOP) { g_b1[b] = base1 - j; g_k2[b] = KTOP - c; break; }
                c += c8[j];
            }
        }
    }
    __syncthreads();
    for (int i = tid; i < 2048; i += 256) g_hist1[b][i] = 0u;   // self-clean
    if (tid == 0) g_arriveA[b] = 0u;
}

// ================= kernel B: refine + hist2 + parallel tail + finalize =======
// grid (BPB, BB), 256 threads, one uint4 per thread
__global__ void __launch_bounds__(256) k_B(float* __restrict__ out) {
    __shared__ unsigned sh3[1024];
    __shared__ unsigned s_w[16];
    __shared__ float s_acc, s_c;
    __shared__ int s_last, s_fin, s_b2;
    __shared__ unsigned s_k3;

    const int b    = blockIdx.y;
    const int tid  = threadIdx.x;
    const int lane = tid & 31;
    const int done = __ldg(&g_done[b]);
    const int b1   = __ldg(&g_b1[b]);

    const uint4 v = ((const uint4*)g_u)[(size_t)b * NU4 + blockIdx.x * 256 + tid];
    unsigned e[4] = {v.x, v.y, v.z, v.w};
    float s = 0.0f;
#pragma unroll
    for (int q = 0; q < 4; q++) {
        unsigned u = e[q];
        if (!u) continue;
        if (done) {
            s += softplus0(unord(u));
        } else {
            int tb = (int)(u >> 21);
            if (tb > b1) s += softplus0(unord(u));
            else if (tb == b1) {
                unsigned idx = atomicAdd(&g_listn[b], 1u);
                g_list[(size_t)b * NELEM + idx] = u;
                atomicAdd(&g_hist2[b][(u >> 10) & 0x7FFu], 1u);
            }
        }
    }
#pragma unroll
    for (int o = 16; o; o >>= 1) s += __shfl_down_sync(0xffffffffu, s, o);
    if (lane == 0 && s != 0.0f) atomicAdd(&g_topsum[b], s);

    // release
    __syncthreads();
    if (tid == 0) {
        fence_rel();
        s_last = (atomicAdd(&g_arriveB[b], 1u) == BPB - 1);
    }
    __syncthreads();
    if (!s_last) return;

    // acquire
    if (tid == 0) fence_acq();
    __syncthreads();

    // ---- per-sample parallel tail ----
    const float kcnt = __ldcg(&g_kcnt[b]);

    if (done) {
        if (tid == 0) g_neg[b] = (kcnt > 0.0f) ? __ldcg(&g_topsum[b]) / kcnt : 0.0f;
        __syncthreads();
    } else {
        const unsigned k2 = __ldcg(&g_k2[b]);
        const unsigned n  = __ldcg(&g_listn[b]);
        const unsigned* lst = g_list + (size_t)b * NELEM;

        // level-2 selection: 8 bins per thread, descending, from g_hist2
        unsigned c8[8]; unsigned cnt = 0;
        const int base2 = 2047 - 8 * tid;
#pragma unroll
        for (int j = 0; j < 8; j++) { c8[j] = __ldcg(&g_hist2[b][base2 - j]); cnt += c8[j]; }
        unsigned pre = bscan(cnt, s_w, tid, lane);
        unsigned excl = pre - cnt;
        if (excl < k2 && pre >= k2) {
            unsigned c = excl;
#pragma unroll
            for (int j = 0; j < 8; j++) {
                if (c + c8[j] >= k2) { s_b2 = base2 - j; s_k3 = k2 - c; break; }
                c += c8[j];
            }
        }
        for (int q = tid; q < 1024; q += 256) sh3[q] = 0u;
        if (tid == 0) { s_acc = 0.0f; s_c = 0.0f; }
        __syncthreads();
        const int b2 = s_b2;
        const unsigned k3 = s_k3;

        // one parallel pass over the compacted list
        float s2 = 0.0f;
        for (unsigned q = tid; q < n; q += 256) {
            unsigned u = __ldcg(&lst[q]);
            int m = (int)((u >> 10) & 0x7FFu);
            if (m > b2) s2 += softplus0(unord(u));
            else if (m == b2) atomicAdd(&sh3[u & 0x3FFu], 1u);
        }
#pragma unroll
        for (int o = 16; o; o >>= 1) s2 += __shfl_down_sync(0xffffffffu, s2, o);
        if (lane == 0 && s2 != 0.0f) atomicAdd(&s_acc, s2);
        __syncthreads();

        // level-3 exact-value bins: 4 bins per thread, parallel softplus
        const unsigned pref = ((unsigned)b1 << 21) | ((unsigned)b2 << 10);
        unsigned c4[4]; unsigned cnt3 = 0; float ws = 0.0f;
        const int base3 = 1023 - 4 * tid;
#pragma unroll
        for (int j = 0; j < 4; j++) {
            unsigned cc = sh3[base3 - j];
            c4[j] = cc; cnt3 += cc;
            if (cc) ws += (float)cc * softplus0(unord(pref | (unsigned)(base3 - j)));
        }
        unsigned pre3 = bscan(cnt3, s_w, tid, lane);
        unsigned excl3 = pre3 - cnt3;
        float contrib = 0.0f;
        if (pre3 <= k3) contrib = ws;
        else if (excl3 < k3) {
            unsigned c = excl3;
#pragma unroll
            for (int j = 0; j < 4; j++) {
                if (!c4[j]) continue;
                float sp = softplus0(unord(pref | (unsigned)(base3 - j)));
                if (c + c4[j] >= k3) { contrib += (float)(k3 - c) * sp; break; }
                contrib += (float)c4[j] * sp;
                c += c4[j];
            }
        }
#pragma unroll
        for (int o = 16; o; o >>= 1) contrib += __shfl_down_sync(0xffffffffu, contrib, o);
        if (lane == 0 && contrib != 0.0f) atomicAdd(&s_c, contrib);
        __syncthreads();
        if (tid == 0) g_neg[b] = (__ldcg(&g_topsum[b]) + s_acc + s_c) / kcnt;
        // self-clean hist2
        for (int q = tid; q < 2048; q += 256) g_hist2[b][q] = 0u;
    }

    // per-sample cleanup, then cross-sample finalize
    if (tid == 0) { g_listn[b] = 0u; g_arriveB[b] = 0u; }
    __syncthreads();
    if (tid == 0) {
        fence_rel();
        s_fin = (atomicAdd(&g_arriveF, 1u) == BB - 1);
    }
    __syncthreads();
    if (s_fin && tid == 0) {
        fence_acq();
        float cls = 0.0f, reg = 0.0f, npsum = 0.0f;
        for (int bb = 0; bb < BB; bb++) {
            float np = (float)__ldcg(&g_npos[bb]);
            float pl = (np > 0.0f) ? 5.0f * __ldcg(&g_pos_sum[bb]) / np : 0.0f;
            float rl = (np > 0.0f) ? __ldcg(&g_reg_sum[bb]) / (4.0f * np) : 0.0f;
            cls += pl + __ldcg(&g_neg[bb]);
            reg += rl;
            npsum += np;
            g_pos_sum[bb] = 0.0f; g_reg_sum[bb] = 0.0f;
            g_topsum[bb] = 0.0f;  g_npos[bb] = 0u;
        }
        g_arriveF = 0u;
        cls *= 0.25f;
        reg *= 0.25f;
        out[0] = cls + 0.5f * reg;
        out[1] = cls;
        out[2] = reg;
        out[3] = npsum;
    }
}

// ---------------- launcher ----------------
extern "C" void kernel_launch(void* const* d_in, const int* in_sizes, int n_in,
                              void* d_out, int out_size) {
    const float* pred = (const float*)d_in[0];   // (4,48,48,48,3,5)
    const float* tgt  = (const float*)d_in[1];   // (4,8,4)
    float* out = (float*)d_out;

    dim3 ga(APB, BB);          // 1296 x 4
    k_A<<<ga, 256>>>(pred, tgt);
    dim3 gb(BPB, BB);          // 324 x 4
    k_B<<<gb, 256>>>(out);
}

// round 14
// speedup vs baseline: 1.0583x; 1.0027x over previous
#include <cuda_runtime.h>
#include <cstdint>

#define BB 4
#define GG 8
#define NVOX 110592            /* 48*48*48 */
#define NELEM 331776           /* NVOX*3 */
#define NU4 (NELEM/4)          /* 82944 */
#define KTOP 800
#define APB (NELEM/256)        /* 1296 blocks per sample, kernel A */
#define BPB (NU4/256)          /* 324 blocks per sample, kernel B */

// ---------------- device scratch (static, zero-init, self-cleaning) ----------
__device__ unsigned g_u[BB*NELEM];
__device__ unsigned g_list[BB*NELEM];
__device__ unsigned g_hist1[BB][2048];
__device__ unsigned g_hist2[BB][2048];
__device__ float    g_pos_sum[BB];
__device__ float    g_reg_sum[BB];
__device__ float    g_topsum[BB];
__device__ float    g_neg[BB];
__device__ float    g_kcnt[BB];
__device__ unsigned g_npos[BB];
__device__ unsigned g_k2[BB];
__device__ unsigned g_listn[BB];
__device__ int      g_done[BB];
__device__ int      g_b1[BB];
__device__ unsigned g_arriveA[BB];
__device__ unsigned g_arriveB[BB];
__device__ unsigned g_arriveF;

// ---------------- helpers ----------------
__device__ __forceinline__ void fence_rel() {
    asm volatile("fence.release.gpu;" ::: "memory");
}
__device__ __forceinline__ void fence_acq() {
    asm volatile("fence.acquire.gpu;" ::: "memory");
}
__device__ __forceinline__ float softplus0(float x) {
    return fmaxf(x, 0.0f) + log1pf(expf(-fabsf(x)));
}
__device__ __forceinline__ float sl1(float x) {
    float ax = fabsf(x);
    return (ax < 1.0f) ? 0.5f * x * x : ax - 0.5f;
}
__device__ __forceinline__ unsigned ordmap(float f) {
    unsigned bb = __float_as_uint(f);
    return (bb & 0x80000000u) ? ~bb : (bb | 0x80000000u);
}
__device__ __forceinline__ float unord(unsigned u) {
    unsigned bb = (u & 0x80000000u) ? (u ^ 0x80000000u) : ~u;
    return __uint_as_float(bb);
}
__device__ __forceinline__ unsigned wscan_incl(unsigned v, int lane) {
#pragma unroll
    for (int o = 1; o < 32; o <<= 1) {
        unsigned t = __shfl_up_sync(0xffffffffu, v, o);
        if (lane >= o) v += t;
    }
    return v;
}
// block-wide inclusive scan over 256 threads (thread 0 = topmost chunk).
__device__ __forceinline__ unsigned bscan(unsigned v, unsigned* s_w, int tid, int lane) {
    unsigned pre = wscan_incl(v, lane);
    if (lane == 31) s_w[tid >> 5] = pre;
    __syncthreads();
    if (tid < 32) {
        unsigned t = (tid < 8) ? s_w[tid] : 0u;
        unsigned p = wscan_incl(t, tid);
        if (tid < 8) s_w[tid + 8] = p - t;      // exclusive warp offset
    }
    __syncthreads();
    return pre + s_w[8 + (tid >> 5)];
}

// ================= kernel A: per-element main pass + parallel level-1 select =
// grid (APB, BB), 256 threads, one (voxel, anchor) element per thread
__global__ void __launch_bounds__(256) k_A(const float* __restrict__ pred,
                                           const float* __restrict__ tgt) {
    __shared__ float s_gxp[GG], s_gxm[GG], s_gyp[GG], s_gym[GG], s_gzp[GG], s_gzm[GG];
    __shared__ float s_gx[GG], s_gy[GG], s_gz[GG], s_gd[GG], s_d3[GG];
    __shared__ unsigned s_hist[2048];
    __shared__ unsigned s_w[16];
    __shared__ unsigned s_total;
    __shared__ int s_last;

    const int b    = blockIdx.y;
    const int tid  = threadIdx.x;
    const int lane = tid & 31;

    if (tid < GG) {
        const float* t = tgt + (b * GG + tid) * 4;
        float gx = t[0], gy = t[1], gz = t[2], gd = t[3];
        float r2 = 0.5f * gd;
        s_gx[tid] = gx; s_gy[tid] = gy; s_gz[tid] = gz; s_gd[tid] = gd;
        s_gxp[tid] = gx + r2; s_gxm[tid] = gx - r2;
        s_gyp[tid] = gy + r2; s_gym[tid] = gy - r2;
        s_gzp[tid] = gz + r2; s_gzm[tid] = gz - r2;
        s_d3[tid] = gd * gd * gd;
    }
    for (int i = tid; i < 2048; i += 256) s_hist[i] = 0u;
    __syncthreads();

    const int e   = blockIdx.x * 256 + tid;          // element = vox*3 + a
    const int vox = e / 3;
    const int a   = e - vox * 3;
    const int w = vox % 48; const int t2 = vox / 48;
    const int h = t2 % 48;  const int d = t2 / 48;
    const float cx = (float)(w * 4 + 2);
    const float cy = (float)(h * 4 + 2);
    const float cz = (float)(d * 4 + 2);

    const float r1 = 2.5f * (float)(1 << a);                         // anchor/2
    const float a3 = 125.0f * (float)(1 << (3 * a));                 // anchor^3
    const float ia = __uint_as_float(0x3E4CCCCDu - ((unsigned)a << 23)); // 0.2/2^a

    const float* p = pred + ((size_t)b * NELEM + (size_t)e) * 5;
    const float conf = p[0];

    float bi = -1.0f, bu = 1.0f;
    int bidx = 0;
#pragma unroll
    for (int g = 0; g < GG; g++) {
        float ix = fminf(cx + r1, s_gxp[g]) - fmaxf(cx - r1, s_gxm[g]); ix = fmaxf(ix, 0.0f);
        float iy = fminf(cy + r1, s_gyp[g]) - fmaxf(cy - r1, s_gym[g]); iy = fmaxf(iy, 0.0f);
        float iz = fminf(cz + r1, s_gzp[g]) - fmaxf(cz - r1, s_gzm[g]); iz = fmaxf(iz, 0.0f);
        float inter = ix * iy * iz;
        float un = a3 + s_d3[g] - inter + 1e-6f;
        if (inter * bu > bi * un) { bi = inter; bu = un; bidx = g; }
    }

    const bool pos = bi > 0.5f  * bu;
    const bool neg = bi < 0.02f * bu;
    unsigned u = 0u;
    if (neg) { u = ordmap(conf); atomicAdd(&s_hist[u >> 21], 1u); }
    g_u[(size_t)b * NELEM + e] = u;

    float lpos = 0.0f, lreg = 0.0f;
    unsigned lnp = 0;
    if (pos) {
        lnp = 1;
        lpos = fmaxf(conf, 0.0f) - conf + log1pf(expf(-fabsf(conf)));
        int g = bidx;
        float tx = (s_gx[g] - cx) * ia;
        float ty = (s_gy[g] - cy) * ia;
        float tz = (s_gz[g] - cz) * ia;
        float td = logf(s_gd[g] * ia);
        lreg = sl1(p[1] - tx) + sl1(p[2] - ty) + sl1(p[3] - tz) + sl1(p[4] - td);
    }
#pragma unroll
    for (int o = 16; o; o >>= 1) {
        lpos += __shfl_down_sync(0xffffffffu, lpos, o);
        lreg += __shfl_down_sync(0xffffffffu, lreg, o);
        lnp  += __shfl_down_sync(0xffffffffu, lnp, o);
    }
    if (lane == 0 && lnp) {
        atomicAdd(&g_pos_sum[b], lpos);
        atomicAdd(&g_reg_sum[b], lreg);
        atomicAdd(&g_npos[b], lnp);
    }
    __syncthreads();
    for (int i = tid; i < 2048; i += 256) {
        unsigned c = s_hist[i];
        if (c) atomicAdd(&g_hist1[b][i], c);
    }
    // release: syncthreads gives block-wide HB into thread 0; thread 0 publishes
    __syncthreads();
    if (tid == 0) {
        fence_rel();
        s_last = (atomicAdd(&g_arriveA[b], 1u) == APB - 1);
    }
    __syncthreads();
    if (!s_last) return;

    // acquire (thread 0) + syncthreads makes all block reads ordered
    if (tid == 0) fence_acq();
    __syncthreads();

    // ---- parallel level-1 selection: 8 bins per thread, descending ----
    unsigned c8[8]; unsigned cnt = 0;
    const int base1 = 2047 - 8 * tid;
#pragma unroll
    for (int j = 0; j < 8; j++) { c8[j] = __ldcg(&g_hist1[b][base1 - j]); cnt += c8[j]; }
    unsigned pre = bscan(cnt, s_w, tid, lane);
    if (tid == 255) s_total = pre;
    __syncthreads();
    const unsigned total = s_total;
    if (total <= KTOP) {
        if (tid == 0) { g_done[b] = 1; g_kcnt[b] = (float)total; }
    } else {
        if (tid == 0) { g_done[b] = 0; g_kcnt[b] = (float)KTOP; }
        unsigned excl = pre - cnt;
        if (excl < KTOP && pre >= KTOP) {
            unsigned c = excl;
#pragma unroll
            for (int j = 0; j < 8; j++) {
                if (c + c8[j] >= KTOP) { g_b1[b] = base1 - j; g_k2[b] = KTOP - c; break; }
                c += c8[j];
            }
        }
    }
    __syncthreads();
    for (int i = tid; i < 2048; i += 256) g_hist1[b][i] = 0u;   // self-clean
    if (tid == 0) g_arriveA[b] = 0u;
}

// ================= kernel B: refine + hist2 + parallel tail + finalize =======
// grid (BPB, BB), 256 threads, one uint4 per thread
__global__ void __launch_bounds__(256) k_B(float* __restrict__ out) {
    __shared__ unsigned sh3[1024];
    __shared__ unsigned s_w[16];
    __shared__ float s_acc, s_c;
    __shared__ int s_last, s_fin, s_b2;
    __shared__ unsigned s_k3;

    const int b    = blockIdx.y;
    const int tid  = threadIdx.x;
    const int lane = tid & 31;
    const int done = __ldg(&g_done[b]);
    const int b1   = __ldg(&g_b1[b]);

    const uint4 v = ((const uint4*)g_u)[(size_t)b * NU4 + blockIdx.x * 256 + tid];
    unsigned e[4] = {v.x, v.y, v.z, v.w};
    float s = 0.0f;
#pragma unroll
    for (int q = 0; q < 4; q++) {
        unsigned u = e[q];
        if (!u) continue;
        if (done) {
            s += softplus0(unord(u));
        } else {
            int tb = (int)(u >> 21);
            if (tb > b1) s += softplus0(unord(u));
            else if (tb == b1) {
                unsigned idx = atomicAdd(&g_listn[b], 1u);
                g_list[(size_t)b * NELEM + idx] = u;
                atomicAdd(&g_hist2[b][(u >> 10) & 0x7FFu], 1u);
            }
        }
    }
#pragma unroll
    for (int o = 16; o; o >>= 1) s += __shfl_down_sync(0xffffffffu, s, o);
    if (lane == 0 && s != 0.0f) atomicAdd(&g_topsum[b], s);

    // release
    __syncthreads();
    if (tid == 0) {
        fence_rel();
        s_last = (atomicAdd(&g_arriveB[b], 1u) == BPB - 1);
    }
    __syncthreads();
    if (!s_last) return;

    // acquire
    if (tid == 0) fence_acq();
    __syncthreads();

    // ---- per-sample parallel tail ----
    const float kcnt = __ldcg(&g_kcnt[b]);

    if (done) {
        if (tid == 0) g_neg[b] = (kcnt > 0.0f) ? __ldcg(&g_topsum[b]) / kcnt : 0.0f;
        __syncthreads();
    } else {
        const unsigned k2 = __ldcg(&g_k2[b]);
        const unsigned n  = __ldcg(&g_listn[b]);
        const unsigned* lst = g_list + (size_t)b * NELEM;

        // level-2 selection: 8 bins per thread, descending, from g_hist2
        unsigned c8[8]; unsigned cnt = 0;
        const int base2 = 2047 - 8 * tid;
#pragma unroll
        for (int j = 0; j < 8; j++) { c8[j] = __ldcg(&g_hist2[b][base2 - j]); cnt += c8[j]; }
        unsigned pre = bscan(cnt, s_w, tid, lane);
        unsigned excl = pre - cnt;
        if (excl < k2 && pre >= k2) {
            unsigned c = excl;
#pragma unroll
            for (int j = 0; j < 8; j++) {
                if (c + c8[j] >= k2) { s_b2 = base2 - j; s_k3 = k2 - c; break; }
                c += c8[j];
            }
        }
        for (int q = tid; q < 1024; q += 256) sh3[q] = 0u;
        if (tid == 0) { s_acc = 0.0f; s_c = 0.0f; }
        __syncthreads();
        const int b2 = s_b2;
        const unsigned k3 = s_k3;

        // one parallel pass over the compacted list
        float s2 = 0.0f;
        for (unsigned q = tid; q < n; q += 256) {
            unsigned u = __ldcg(&lst[q]);
            int m = (int)((u >> 10) & 0x7FFu);
            if (m > b2) s2 += softplus0(unord(u));
            else if (m == b2) atomicAdd(&sh3[u & 0x3FFu], 1u);
        }
#pragma unroll
        for (int o = 16; o; o >>= 1) s2 += __shfl_down_sync(0xffffffffu, s2, o);
        if (lane == 0 && s2 != 0.0f) atomicAdd(&s_acc, s2);
        __syncthreads();

        // level-3 exact-value bins: 4 bins per thread, parallel softplus
        const unsigned pref = ((unsigned)b1 << 21) | ((unsigned)b2 << 10);
        unsigned c4[4]; unsigned cnt3 = 0; float ws = 0.0f;
        const int base3 = 1023 - 4 * tid;
#pragma unroll
        for (int j = 0; j < 4; j++) {
            unsigned cc = sh3[base3 - j];
            c4[j] = cc; cnt3 += cc;
            if (cc) ws += (float)cc * softplus0(unord(pref | (unsigned)(base3 - j)));
        }
        unsigned pre3 = bscan(cnt3, s_w, tid, lane);
        unsigned excl3 = pre3 - cnt3;
        float contrib = 0.0f;
        if (pre3 <= k3) contrib = ws;
        else if (excl3 < k3) {
            unsigned c = excl3;
#pragma unroll
            for (int j = 0; j < 4; j++) {
                if (!c4[j]) continue;
                float sp = softplus0(unord(pref | (unsigned)(base3 - j)));
                if (c + c4[j] >= k3) { contrib += (float)(k3 - c) * sp; break; }
                contrib += (float)c4[j] * sp;
                c += c4[j];
            }
        }
#pragma unroll
        for (int o = 16; o; o >>= 1) contrib += __shfl_down_sync(0xffffffffu, contrib, o);
        if (lane == 0 && contrib != 0.0f) atomicAdd(&s_c, contrib);
        __syncthreads();
        if (tid == 0) g_neg[b] = (__ldcg(&g_topsum[b]) + s_acc + s_c) / kcnt;
        // self-clean hist2
        for (int q = tid; q < 2048; q += 256) g_hist2[b][q] = 0u;
    }

    // per-sample cleanup, then cross-sample finalize
    if (tid == 0) { g_listn[b] = 0u; g_arriveB[b] = 0u; }
    __syncthreads();
    if (tid == 0) {
        fence_rel();
        s_fin = (atomicAdd(&g_arriveF, 1u) == BB - 1);
    }
    __syncthreads();
    if (s_fin && tid == 0) {
        fence_acq();
        float cls = 0.0f, reg = 0.0f, npsum = 0.0f;
        for (int bb = 0; bb < BB; bb++) {
            float np = (float)__ldcg(&g_npos[bb]);
            float pl = (np > 0.0f) ? 5.0f * __ldcg(&g_pos_sum[bb]) / np : 0.0f;
            float rl = (np > 0.0f) ? __ldcg(&g_reg_sum[bb]) / (4.0f * np) : 0.0f;
            cls += pl + __ldcg(&g_neg[bb]);
            reg += rl;
            npsum += np;
            g_pos_sum[bb] = 0.0f; g_reg_sum[bb] = 0.0f;
            g_topsum[bb] = 0.0f;  g_npos[bb] = 0u;
        }
        g_arriveF = 0u;
        cls *= 0.25f;
        reg *= 0.25f;
        out[0] = cls + 0.5f * reg;
        out[1] = cls;
        out[2] = reg;
        out[3] = npsum;
    }
}

// ---------------- launcher ----------------
extern "C" void kernel_launch(void* const* d_in, const int* in_sizes, int n_in,
                              void* d_out, int out_size) {
    const float* pred = (const float*)d_in[0];   // (4,48,48,48,3,5)
    const float* tgt  = (const float*)d_in[1];   // (4,8,4)
    float* out = (float*)d_out;

    dim3 ga(APB, BB);          // 1296 x 4
    k_A<<<ga, 256>>>(pred, tgt);
    dim3 gb(BPB, BB);          // 324 x 4
    k_B<<<gb, 256>>>(out);
}

// round 15
// speedup vs baseline: 1.4620x; 1.3814x over previous
#include <cuda_runtime.h>
#include <cstdint>

#define BB 4
#define GG 8
#define NVOX 110592            /* 48*48*48 */
#define NELEM 331776           /* NVOX*3 */
#define KTOP 800
#define APB (NELEM/256)        /* 1296 blocks per sample, kernel A */
#define CAP 16384              /* candidate list capacity per sample */
#define CTH 0xC0000000u        /* ordmap(2.0f): candidate threshold conf > 2.0 */

// ---------------- device scratch (static, zero-init, self-cleaning) ----------
__device__ unsigned g_cand[BB*CAP];
__device__ float    g_pos_sum[BB];
__device__ float    g_reg_sum[BB];
__device__ float    g_neg[BB];
__device__ unsigned g_npos[BB];
__device__ unsigned g_listn[BB];
__device__ unsigned g_negcnt[BB];
__device__ int      g_fb[BB];
__device__ unsigned g_arriveF;

// ---------------- helpers ----------------
__device__ __forceinline__ void fence_rel() { asm volatile("fence.release.gpu;" ::: "memory"); }
__device__ __forceinline__ void fence_acq() { asm volatile("fence.acquire.gpu;" ::: "memory"); }
__device__ __forceinline__ float softplus0(float x) {
    return fmaxf(x, 0.0f) + log1pf(expf(-fabsf(x)));
}
__device__ __forceinline__ float sl1(float x) {
    float ax = fabsf(x);
    return (ax < 1.0f) ? 0.5f * x * x : ax - 0.5f;
}
__device__ __forceinline__ unsigned ordmap(float f) {
    unsigned bb = __float_as_uint(f);
    return (bb & 0x80000000u) ? ~bb : (bb | 0x80000000u);
}
__device__ __forceinline__ float unord(unsigned u) {
    unsigned bb = (u & 0x80000000u) ? (u ^ 0x80000000u) : ~u;
    return __uint_as_float(bb);
}
__device__ __forceinline__ unsigned wscan_incl(unsigned v, int lane) {
#pragma unroll
    for (int o = 1; o < 32; o <<= 1) {
        unsigned t = __shfl_up_sync(0xffffffffu, v, o);
        if (lane >= o) v += t;
    }
    return v;
}
// block-wide inclusive scan for 1024 threads; s_w needs 64 entries
__device__ __forceinline__ unsigned bscan1024(unsigned v, unsigned* s_w, int tid, int lane) {
    unsigned pre = wscan_incl(v, lane);
    if (lane == 31) s_w[tid >> 5] = pre;
    __syncthreads();
    if (tid < 32) {
        unsigned t = s_w[tid];
        unsigned p = wscan_incl(t, tid);
        s_w[32 + tid] = p - t;
    }
    __syncthreads();
    return pre + s_w[32 + (tid >> 5)];
}

// ================= kernel A: lean main pass (map + compact) ==================
// grid (APB, BB), 256 threads, one (voxel, anchor) element per thread
__global__ void __launch_bounds__(256) k_A(const float* __restrict__ pred,
                                           const float* __restrict__ tgt) {
    __shared__ float s_gxp[GG], s_gxm[GG], s_gyp[GG], s_gym[GG], s_gzp[GG], s_gzm[GG];
    __shared__ float s_gx[GG], s_gy[GG], s_gz[GG], s_gd[GG], s_d3[GG];
    __shared__ unsigned s_wcnt[8];

    const int b    = blockIdx.y;
    const int tid  = threadIdx.x;
    const int lane = tid & 31;
    const int wid  = tid >> 5;

    if (tid < GG) {
        const float* t = tgt + (b * GG + tid) * 4;
        float gx = t[0], gy = t[1], gz = t[2], gd = t[3];
        float r2 = 0.5f * gd;
        s_gx[tid] = gx; s_gy[tid] = gy; s_gz[tid] = gz; s_gd[tid] = gd;
        s_gxp[tid] = gx + r2; s_gxm[tid] = gx - r2;
        s_gyp[tid] = gy + r2; s_gym[tid] = gy - r2;
        s_gzp[tid] = gz + r2; s_gzm[tid] = gz - r2;
        s_d3[tid] = gd * gd * gd;
    }
    __syncthreads();

    const int e   = blockIdx.x * 256 + tid;          // element = vox*3 + a
    const int vox = e / 3;
    const int a   = e - vox * 3;
    const int w = vox % 48; const int t2 = vox / 48;
    const int h = t2 % 48;  const int d = t2 / 48;
    const float cx = (float)(w * 4 + 2);
    const float cy = (float)(h * 4 + 2);
    const float cz = (float)(d * 4 + 2);

    const float r1 = 2.5f * (float)(1 << a);                         // anchor/2
    const float a3 = 125.0f * (float)(1 << (3 * a));                 // anchor^3
    const float ia = __uint_as_float(0x3E4CCCCDu - ((unsigned)a << 23)); // 0.2/2^a

    const float* p = pred + ((size_t)b * NELEM + (size_t)e) * 5;
    const float conf = p[0];

    float bi = -1.0f, bu = 1.0f;
    int bidx = 0;
#pragma unroll
    for (int g = 0; g < GG; g++) {
        float ix = fminf(cx + r1, s_gxp[g]) - fmaxf(cx - r1, s_gxm[g]); ix = fmaxf(ix, 0.0f);
        float iy = fminf(cy + r1, s_gyp[g]) - fmaxf(cy - r1, s_gym[g]); iy = fmaxf(iy, 0.0f);
        float iz = fminf(cz + r1, s_gzp[g]) - fmaxf(cz - r1, s_gzm[g]); iz = fmaxf(iz, 0.0f);
        float inter = ix * iy * iz;
        float un = a3 + s_d3[g] - inter + 1e-6f;
        if (inter * bu > bi * un) { bi = inter; bu = un; bidx = g; }
    }

    const bool pos = bi > 0.5f  * bu;
    const bool neg = bi < 0.02f * bu;
    const unsigned u = neg ? ordmap(conf) : 0u;

    // negative count: per-warp popc -> block reduce -> one RED per block
    unsigned nm = __popc(__ballot_sync(0xffffffffu, neg));
    if (lane == 0) s_wcnt[wid] = nm;

    // candidate compaction (conf > 2.0): warp-aggregated global push
    const bool cand = neg && (u > CTH);
    unsigned cm = __ballot_sync(0xffffffffu, cand);
    if (cm) {
        int leader = __ffs(cm) - 1;
        unsigned base = 0u;
        if (lane == leader) base = atomicAdd(&g_listn[b], (unsigned)__popc(cm));
        base = __shfl_sync(0xffffffffu, base, leader);
        if (cand) {
            unsigned idx = base + __popc(cm & ((1u << lane) - 1u));
            if (idx < CAP) g_cand[b * CAP + idx] = u;
        }
    }

    // pos losses
    float lpos = 0.0f, lreg = 0.0f;
    unsigned lnp = 0;
    if (pos) {
        lnp = 1;
        lpos = fmaxf(conf, 0.0f) - conf + log1pf(expf(-fabsf(conf)));
        int g = bidx;
        float tx = (s_gx[g] - cx) * ia;
        float ty = (s_gy[g] - cy) * ia;
        float tz = (s_gz[g] - cz) * ia;
        float td = logf(s_gd[g] * ia);
        lreg = sl1(p[1] - tx) + sl1(p[2] - ty) + sl1(p[3] - tz) + sl1(p[4] - td);
    }
#pragma unroll
    for (int o = 16; o; o >>= 1) {
        lpos += __shfl_down_sync(0xffffffffu, lpos, o);
        lreg += __shfl_down_sync(0xffffffffu, lreg, o);
        lnp  += __shfl_down_sync(0xffffffffu, lnp, o);
    }
    if (lane == 0 && lnp) {
        atomicAdd(&g_pos_sum[b], lpos);
        atomicAdd(&g_reg_sum[b], lreg);
        atomicAdd(&g_npos[b], lnp);
    }
    __syncthreads();
    if (tid == 0) {
        unsigned tot = 0;
#pragma unroll
        for (int q = 0; q < 8; q++) tot += s_wcnt[q];
        atomicAdd(&g_negcnt[b], tot);    // no return needed -> RED
    }
}

// ================= kernel T: exact top-800 on candidate list =================
// grid (BB), 1024 threads, one block per sample
__global__ void __launch_bounds__(1024) k_T() {
    __shared__ unsigned sh[2048];
    __shared__ unsigned s_w[64];
    __shared__ float s_sum;
    __shared__ int s_b1, s_b2;
    __shared__ unsigned s_k2, s_k3;

    const int b    = blockIdx.x;
    const int tid  = threadIdx.x;
    const int lane = tid & 31;

    const unsigned listn  = g_listn[b];
    const unsigned negcnt = g_negcnt[b];

    if (!(negcnt > KTOP && listn >= KTOP && listn <= CAP)) {
        if (tid == 0) g_fb[b] = 1;       // fallback needed
        return;
    }
    if (tid == 0) { g_fb[b] = 0; s_sum = 0.0f; }
    const unsigned n = listn;
    const unsigned* lst = g_cand + b * CAP;

    // ---- level 1: hist over u>>21 ----
    sh[tid] = 0u; sh[tid + 1024] = 0u;
    __syncthreads();
    for (unsigned q = tid; q < n; q += 1024)
        atomicAdd(&sh[lst[q] >> 21], 1u);
    __syncthreads();
    {
        const int base = 2047 - 2 * tid;
        unsigned c0 = sh[base], c1 = sh[base - 1];
        unsigned cnt = c0 + c1;
        unsigned pre = bscan1024(cnt, s_w, tid, lane);
        unsigned excl = pre - cnt;
        if (excl < KTOP && pre >= KTOP) {
            if (excl + c0 >= KTOP) { s_b1 = base;     s_k2 = KTOP - excl; }
            else                   { s_b1 = base - 1; s_k2 = KTOP - excl - c0; }
        }
    }
    __syncthreads();
    const int b1 = s_b1;
    const unsigned k2 = s_k2;

    // ---- pass 2: sum above b1; mid-hist for == b1 ----
    sh[tid] = 0u; sh[tid + 1024] = 0u;
    __syncthreads();
    float s = 0.0f;
    for (unsigned q = tid; q < n; q += 1024) {
        unsigned u = lst[q];
        int tb = (int)(u >> 21);
        if (tb > b1) s += softplus0(unord(u));
        else if (tb == b1) atomicAdd(&sh[(u >> 10) & 0x7FFu], 1u);
    }
#pragma unroll
    for (int o = 16; o; o >>= 1) s += __shfl_down_sync(0xffffffffu, s, o);
    if (lane == 0 && s != 0.0f) atomicAdd(&s_sum, s);
    __syncthreads();
    {
        const int base = 2047 - 2 * tid;
        unsigned c0 = sh[base], c1 = sh[base - 1];
        unsigned cnt = c0 + c1;
        unsigned pre = bscan1024(cnt, s_w, tid, lane);
        unsigned excl = pre - cnt;
        if (excl < k2 && pre >= k2) {
            if (excl + c0 >= k2) { s_b2 = base;     s_k3 = k2 - excl; }
            else                 { s_b2 = base - 1; s_k3 = k2 - excl - c0; }
        }
    }
    __syncthreads();
    const int b2 = s_b2;
    const unsigned k3 = s_k3;

    // ---- pass 3: sum mid>b2; exact-value hist for == b2 ----
    if (tid < 1024) sh[tid] = 0u;
    __syncthreads();
    float s2 = 0.0f;
    for (unsigned q = tid; q < n; q += 1024) {
        unsigned u = lst[q];
        if ((int)(u >> 21) != b1) continue;
        int m = (int)((u >> 10) & 0x7FFu);
        if (m > b2) s2 += softplus0(unord(u));
        else if (m == b2) atomicAdd(&sh[u & 0x3FFu], 1u);
    }
#pragma unroll
    for (int o = 16; o; o >>= 1) s2 += __shfl_down_sync(0xffffffffu, s2, o);
    if (lane == 0 && s2 != 0.0f) atomicAdd(&s_sum, s2);
    __syncthreads();

    // ---- level 3: exact bins, closed form ----
    {
        const unsigned pref = ((unsigned)b1 << 21) | ((unsigned)b2 << 10);
        const int bin = 1023 - tid;
        unsigned cnt = sh[bin];
        float sp = cnt ? softplus0(unord(pref | (unsigned)bin)) : 0.0f;
        unsigned pre = bscan1024(cnt, s_w, tid, lane);
        unsigned excl = pre - cnt;
        float contrib = 0.0f;
        if (pre <= k3) contrib = (float)cnt * sp;
        else if (excl < k3) contrib = (float)(k3 - excl) * sp;
#pragma unroll
        for (int o = 16; o; o >>= 1) contrib += __shfl_down_sync(0xffffffffu, contrib, o);
        if (lane == 0 && contrib != 0.0f) atomicAdd(&s_sum, contrib);
    }
    __syncthreads();
    if (tid == 0) g_neg[b] = s_sum / (float)KTOP;
}

// ================= kernel CF: fallback (exact, rarely taken) + finalize ======
// grid (BB), 1024 threads
__global__ void __launch_bounds__(1024) k_CF(const float* __restrict__ pred,
                                             const float* __restrict__ tgt,
                                             float* __restrict__ out) {
    __shared__ float s_gxp[GG], s_gxm[GG], s_gyp[GG], s_gym[GG], s_gzp[GG], s_gzm[GG];
    __shared__ unsigned sh[2048];
    __shared__ unsigned s_w[64];
    __shared__ float s_sum;
    __shared__ float s_d3s[GG];
    __shared__ int s_b1, s_b2, s_fin;
    __shared__ unsigned s_k2, s_k3;

    const int b    = blockIdx.x;
    const int tid  = threadIdx.x;
    const int lane = tid & 31;

    if (g_fb[b]) {
        // ---- exact fallback: recompute u per element, 3-level selection ----
        if (tid < GG) {
            const float* t = tgt + (b * GG + tid) * 4;
            float gx = t[0], gy = t[1], gz = t[2], gd = t[3];
            float r2 = 0.5f * gd;
            s_gxp[tid] = gx + r2; s_gxm[tid] = gx - r2;
            s_gyp[tid] = gy + r2; s_gym[tid] = gy - r2;
            s_gzp[tid] = gz + r2; s_gzm[tid] = gz - r2;
            s_d3s[tid] = gd * gd * gd;
        }
        if (tid == 0) s_sum = 0.0f;
        __syncthreads();

        const unsigned negcnt = g_negcnt[b];
        const unsigned kcnt = (negcnt < KTOP) ? negcnt : KTOP;

        // helper lambda: compute u for element e (0 if not negative)
        auto calc_u = [&](int e) -> unsigned {
            int vox = e / 3;
            int a   = e - vox * 3;
            int w = vox % 48; int t2 = vox / 48;
            int h = t2 % 48;  int d = t2 / 48;
            float cx = (float)(w * 4 + 2);
            float cy = (float)(h * 4 + 2);
            float cz = (float)(d * 4 + 2);
            float r1 = 2.5f * (float)(1 << a);
            float a3 = 125.0f * (float)(1 << (3 * a));
            float bi = -1.0f, bu = 1.0f;
#pragma unroll
            for (int g = 0; g < GG; g++) {
                float ix = fminf(cx + r1, s_gxp[g]) - fmaxf(cx - r1, s_gxm[g]); ix = fmaxf(ix, 0.0f);
                float iy = fminf(cy + r1, s_gyp[g]) - fmaxf(cy - r1, s_gym[g]); iy = fmaxf(iy, 0.0f);
                float iz = fminf(cz + r1, s_gzp[g]) - fmaxf(cz - r1, s_gzm[g]); iz = fmaxf(iz, 0.0f);
                float inter = ix * iy * iz;
                float un = a3 + s_d3s[g] - inter + 1e-6f;
                if (inter * bu > bi * un) { bi = inter; bu = un; }
            }
            if (!(bi < 0.02f * bu)) return 0u;
            float conf = pred[((size_t)b * NELEM + (size_t)e) * 5];
            return ordmap(conf);
        };

        if (negcnt <= KTOP) {
            // sum softplus over ALL negatives
            float s = 0.0f;
            for (int e = tid; e < NELEM; e += 1024) {
                unsigned u = calc_u(e);
                if (u) s += softplus0(unord(u));
            }
#pragma unroll
            for (int o = 16; o; o >>= 1) s += __shfl_down_sync(0xffffffffu, s, o);
            if (lane == 0 && s != 0.0f) atomicAdd(&s_sum, s);
            __syncthreads();
            if (tid == 0) g_neg[b] = (kcnt > 0) ? s_sum / (float)kcnt : 0.0f;
        } else {
            // level 1
            sh[tid] = 0u; sh[tid + 1024] = 0u;
            __syncthreads();
            for (int e = tid; e < NELEM; e += 1024) {
                unsigned u = calc_u(e);
                if (u) atomicAdd(&sh[u >> 21], 1u);
            }
            __syncthreads();
            {
                const int base = 2047 - 2 * tid;
                unsigned c0 = sh[base], c1 = sh[base - 1];
                unsigned cnt = c0 + c1;
                unsigned pre = bscan1024(cnt, s_w, tid, lane);
                unsigned excl = pre - cnt;
                if (excl < KTOP && pre >= KTOP) {
                    if (excl + c0 >= KTOP) { s_b1 = base;     s_k2 = KTOP - excl; }
                    else                   { s_b1 = base - 1; s_k2 = KTOP - excl - c0; }
                }
            }
            __syncthreads();
            const int b1 = s_b1; const unsigned k2 = s_k2;
            // pass 2
            sh[tid] = 0u; sh[tid + 1024] = 0u;
            __syncthreads();
            float s = 0.0f;
            for (int e = tid; e < NELEM; e += 1024) {
                unsigned u = calc_u(e);
                if (!u) continue;
                int tb = (int)(u >> 21);
                if (tb > b1) s += softplus0(unord(u));
                else if (tb == b1) atomicAdd(&sh[(u >> 10) & 0x7FFu], 1u);
            }
#pragma unroll
            for (int o = 16; o; o >>= 1) s += __shfl_down_sync(0xffffffffu, s, o);
            if (lane == 0 && s != 0.0f) atomicAdd(&s_sum, s);
            __syncthreads();
            {
                const int base = 2047 - 2 * tid;
                unsigned c0 = sh[base], c1 = sh[base - 1];
                unsigned cnt = c0 + c1;
                unsigned pre = bscan1024(cnt, s_w, tid, lane);
                unsigned excl = pre - cnt;
                if (excl < k2 && pre >= k2) {
                    if (excl + c0 >= k2) { s_b2 = base;     s_k3 = k2 - excl; }
                    else                 { s_b2 = base - 1; s_k3 = k2 - excl - c0; }
                }
            }
            __syncthreads();
            const int b2 = s_b2; const unsigned k3 = s_k3;
            // pass 3
            if (tid < 1024) sh[tid] = 0u;
            __syncthreads();
            float s2 = 0.0f;
            for (int e = tid; e < NELEM; e += 1024) {
                unsigned u = calc_u(e);
                if (!u || (int)(u >> 21) != b1) continue;
                int m = (int)((u >> 10) & 0x7FFu);
                if (m > b2) s2 += softplus0(unord(u));
                else if (m == b2) atomicAdd(&sh[u & 0x3FFu], 1u);
            }
#pragma unroll
            for (int o = 16; o; o >>= 1) s2 += __shfl_down_sync(0xffffffffu, s2, o);
            if (lane == 0 && s2 != 0.0f) atomicAdd(&s_sum, s2);
            __syncthreads();
            {
                const unsigned pref = ((unsigned)b1 << 21) | ((unsigned)b2 << 10);
                const int bin = 1023 - tid;
                unsigned cnt = sh[bin];
                float sp = cnt ? softplus0(unord(pref | (unsigned)bin)) : 0.0f;
                unsigned pre = bscan1024(cnt, s_w, tid, lane);
                unsigned excl = pre - cnt;
                float contrib = 0.0f;
                if (pre <= k3) contrib = (float)cnt * sp;
                else if (excl < k3) contrib = (float)(k3 - excl) * sp;
#pragma unroll
                for (int o = 16; o; o >>= 1) contrib += __shfl_down_sync(0xffffffffu, contrib, o);
                if (lane == 0 && contrib != 0.0f) atomicAdd(&s_sum, contrib);
            }
            __syncthreads();
            if (tid == 0) g_neg[b] = s_sum / (float)KTOP;
        }
    }

    // ---- arrive; last block finalizes + cleans ----
    __syncthreads();
    if (tid == 0) {
        fence_rel();
        s_fin = (atomicAdd(&g_arriveF, 1u) == BB - 1);
    }
    __syncthreads();
    if (s_fin && tid == 0) {
        fence_acq();
        float cls = 0.0f, reg = 0.0f, npsum = 0.0f;
        for (int bb = 0; bb < BB; bb++) {
            float np = (float)g_npos[bb];
            float pl = (np > 0.0f) ? 5.0f * g_pos_sum[bb] / np : 0.0f;
            float rl = (np > 0.0f) ? g_reg_sum[bb] / (4.0f * np) : 0.0f;
            cls += pl + g_neg[bb];
            reg += rl;
            npsum += np;
            g_pos_sum[bb] = 0.0f; g_reg_sum[bb] = 0.0f;
            g_npos[bb] = 0u; g_listn[bb] = 0u; g_negcnt[bb] = 0u;
        }
        g_arriveF = 0u;
        cls *= 0.25f;
        reg *= 0.25f;
        out[0] = cls + 0.5f * reg;
        out[1] = cls;
        out[2] = reg;
        out[3] = npsum;
    }
}

// ---------------- launcher ----------------
extern "C" void kernel_launch(void* const* d_in, const int* in_sizes, int n_in,
                              void* d_out, int out_size) {
    const float* pred = (const float*)d_in[0];   // (4,48,48,48,3,5)
    const float* tgt  = (const float*)d_in[1];   // (4,8,4)
    float* out = (float*)d_out;

    dim3 ga(APB, BB);            // 1296 x 4
    k_A<<<ga, 256>>>(pred, tgt);
    k_T<<<BB, 1024>>>();
    k_CF<<<BB, 1024>>>(pred, tgt, out);
}

// round 16
// speedup vs baseline: 1.5014x; 1.0269x over previous
#include <cuda_runtime.h>
#include <cstdint>

#define BB 4
#define GG 8
#define NVOX 110592            /* 48*48*48 */
#define NELEM 331776           /* NVOX*3 */
#define KTOP 800
#define APB (NELEM/256)        /* 1296 blocks per sample, kernel A */
#define CAP 16384              /* candidate list capacity per sample */
#define CTH 0xC0000000u        /* ordmap(2.0f): candidate threshold conf > 2.0 */

// ---------------- device scratch (static, zero-init, self-cleaning) ----------
__device__ unsigned g_cand[BB*CAP];
__device__ float    g_pos_sum[BB];
__device__ float    g_reg_sum[BB];
__device__ float    g_neg[BB];
__device__ unsigned g_npos[BB];
__device__ unsigned g_listn[BB];
__device__ unsigned g_negcnt[BB];
__device__ unsigned g_arriveF;

// ---------------- helpers ----------------
__device__ __forceinline__ void fence_rel() { asm volatile("fence.release.gpu;" ::: "memory"); }
__device__ __forceinline__ void fence_acq() { asm volatile("fence.acquire.gpu;" ::: "memory"); }
__device__ __forceinline__ float softplus0(float x) {
    return fmaxf(x, 0.0f) + log1pf(expf(-fabsf(x)));
}
__device__ __forceinline__ float sl1(float x) {
    float ax = fabsf(x);
    return (ax < 1.0f) ? 0.5f * x * x : ax - 0.5f;
}
__device__ __forceinline__ unsigned ordmap(float f) {
    unsigned bb = __float_as_uint(f);
    return (bb & 0x80000000u) ? ~bb : (bb | 0x80000000u);
}
__device__ __forceinline__ float unord(unsigned u) {
    unsigned bb = (u & 0x80000000u) ? (u ^ 0x80000000u) : ~u;
    return __uint_as_float(bb);
}
__device__ __forceinline__ unsigned wscan_incl(unsigned v, int lane) {
#pragma unroll
    for (int o = 1; o < 32; o <<= 1) {
        unsigned t = __shfl_up_sync(0xffffffffu, v, o);
        if (lane >= o) v += t;
    }
    return v;
}
// block-wide inclusive scan for 1024 threads; s_w needs 64 entries
__device__ __forceinline__ unsigned bscan1024(unsigned v, unsigned* s_w, int tid, int lane) {
    unsigned pre = wscan_incl(v, lane);
    if (lane == 31) s_w[tid >> 5] = pre;
    __syncthreads();
    if (tid < 32) {
        unsigned t = s_w[tid];
        unsigned p = wscan_incl(t, tid);
        s_w[32 + tid] = p - t;
    }
    __syncthreads();
    return pre + s_w[32 + (tid >> 5)];
}

// ================= kernel A: lean main pass with geometric fast path =========
// grid (APB, BB), 256 threads, one (voxel, anchor) element per thread
__global__ void __launch_bounds__(256) k_A(const float* __restrict__ pred,
                                           const float* __restrict__ tgt) {
    __shared__ float s_gxp[GG], s_gxm[GG], s_gyp[GG], s_gym[GG], s_gzp[GG], s_gzm[GG];
    __shared__ float s_gx[GG], s_gy[GG], s_gz[GG], s_gd[GG], s_d3[GG];
    __shared__ int s_mx[48], s_my[48], s_mz[48];
    __shared__ unsigned s_wcnt[8];

    const int b    = blockIdx.y;
    const int tid  = threadIdx.x;
    const int lane = tid & 31;
    const int wid  = tid >> 5;

    if (tid < GG) {
        const float* t = tgt + (b * GG + tid) * 4;
        float gx = t[0], gy = t[1], gz = t[2], gd = t[3];
        float r2 = 0.5f * gd;
        s_gx[tid] = gx; s_gy[tid] = gy; s_gz[tid] = gz; s_gd[tid] = gd;
        s_gxp[tid] = gx + r2; s_gxm[tid] = gx - r2;
        s_gyp[tid] = gy + r2; s_gym[tid] = gy - r2;
        s_gzp[tid] = gz + r2; s_gzm[tid] = gz - r2;
        s_d3[tid] = gd * gd * gd;
    }
    __syncthreads();

    // per-axis GT overlap masks at the largest anchor (r1 = 10):
    // bit g set  <=>  axis overlap > 0 possible for that coordinate
    if (tid < 144) {
        int axis  = tid / 48;
        int coord = tid - axis * 48;
        float c = (float)(coord * 4 + 2);
        unsigned m = 0u;
#pragma unroll
        for (int g = 0; g < GG; g++) {
            float gp = (axis == 0) ? s_gxp[g] : (axis == 1) ? s_gyp[g] : s_gzp[g];
            float gm = (axis == 0) ? s_gxm[g] : (axis == 1) ? s_gym[g] : s_gzm[g];
            if ((c + 10.0f > gm) && (gp > c - 10.0f)) m |= (1u << g);
        }
        if (axis == 0) s_mx[coord] = (int)m;
        else if (axis == 1) s_my[coord] = (int)m;
        else s_mz[coord] = (int)m;
    }
    __syncthreads();

    const int e   = blockIdx.x * 256 + tid;          // element = vox*3 + a
    const int vox = e / 3;
    const int a   = e - vox * 3;
    const int w = vox % 48; const int t2 = vox / 48;
    const int h = t2 % 48;  const int d = t2 / 48;

    const float* p = pred + ((size_t)b * NELEM + (size_t)e) * 5;
    const float conf = p[0];

    bool pos = false, neg = true;
    int bidx = 0;
    float bi = -1.0f, bu = 1.0f;

    const bool far = ((s_mx[w] & s_my[h] & s_mz[d]) == 0);
    if (!far) {
        // exact 8-GT IoU comparison loop (cross-multiplied, division-free)
        const float cx = (float)(w * 4 + 2);
        const float cy = (float)(h * 4 + 2);
        const float cz = (float)(d * 4 + 2);
        const float r1 = 2.5f * (float)(1 << a);
        const float a3 = 125.0f * (float)(1 << (3 * a));
#pragma unroll
        for (int g = 0; g < GG; g++) {
            float ix = fminf(cx + r1, s_gxp[g]) - fmaxf(cx - r1, s_gxm[g]); ix = fmaxf(ix, 0.0f);
            float iy = fminf(cy + r1, s_gyp[g]) - fmaxf(cy - r1, s_gym[g]); iy = fmaxf(iy, 0.0f);
            float iz = fminf(cz + r1, s_gzp[g]) - fmaxf(cz - r1, s_gzm[g]); iz = fmaxf(iz, 0.0f);
            float inter = ix * iy * iz;
            float un = a3 + s_d3[g] - inter + 1e-6f;
            if (inter * bu > bi * un) { bi = inter; bu = un; bidx = g; }
        }
        pos = bi > 0.5f  * bu;
        neg = bi < 0.02f * bu;
    }

    const unsigned u = neg ? ordmap(conf) : 0u;

    // negative count: per-warp popc -> block reduce -> one RED per block
    unsigned nm = __popc(__ballot_sync(0xffffffffu, neg));
    if (lane == 0) s_wcnt[wid] = nm;

    // candidate compaction (conf > 2.0): warp-aggregated global push
    const bool cand = neg && (u > CTH);
    unsigned cm = __ballot_sync(0xffffffffu, cand);
    if (cm) {
        int leader = __ffs(cm) - 1;
        unsigned base = 0u;
        if (lane == leader) base = atomicAdd(&g_listn[b], (unsigned)__popc(cm));
        base = __shfl_sync(0xffffffffu, base, leader);
        if (cand) {
            unsigned idx = base + __popc(cm & ((1u << lane) - 1u));
            if (idx < CAP) g_cand[b * CAP + idx] = u;
        }
    }

    // pos losses (rare)
    if (__ballot_sync(0xffffffffu, pos)) {
        float lpos = 0.0f, lreg = 0.0f;
        unsigned lnp = 0;
        if (pos) {
            const float cx = (float)(w * 4 + 2);
            const float cy = (float)(h * 4 + 2);
            const float cz = (float)(d * 4 + 2);
            const float ia = __uint_as_float(0x3E4CCCCDu - ((unsigned)a << 23)); // 0.2/2^a
            lnp = 1;
            lpos = fmaxf(conf, 0.0f) - conf + log1pf(expf(-fabsf(conf)));
            int g = bidx;
            float tx = (s_gx[g] - cx) * ia;
            float ty = (s_gy[g] - cy) * ia;
            float tz = (s_gz[g] - cz) * ia;
            float td = logf(s_gd[g] * ia);
            lreg = sl1(p[1] - tx) + sl1(p[2] - ty) + sl1(p[3] - tz) + sl1(p[4] - td);
        }
#pragma unroll
        for (int o = 16; o; o >>= 1) {
            lpos += __shfl_down_sync(0xffffffffu, lpos, o);
            lreg += __shfl_down_sync(0xffffffffu, lreg, o);
            lnp  += __shfl_down_sync(0xffffffffu, lnp, o);
        }
        if (lane == 0 && lnp) {
            atomicAdd(&g_pos_sum[b], lpos);
            atomicAdd(&g_reg_sum[b], lreg);
            atomicAdd(&g_npos[b], lnp);
        }
    }
    __syncthreads();
    if (tid == 0) {
        unsigned tot = 0;
#pragma unroll
        for (int q = 0; q < 8; q++) tot += s_wcnt[q];
        atomicAdd(&g_negcnt[b], tot);
    }
}

// ================= kernel F: select (list or exact fallback) + finalize ======
// grid (BB), 1024 threads, one block per sample
__global__ void __launch_bounds__(1024) k_F(const float* __restrict__ pred,
                                            const float* __restrict__ tgt,
                                            float* __restrict__ out) {
    __shared__ float s_gxp[GG], s_gxm[GG], s_gyp[GG], s_gym[GG], s_gzp[GG], s_gzm[GG];
    __shared__ unsigned sh[2048];
    __shared__ unsigned s_w[64];
    __shared__ float s_sum;
    __shared__ float s_d3s[GG];
    __shared__ int s_b1, s_b2, s_fin;
    __shared__ unsigned s_k2, s_k3;

    const int b    = blockIdx.x;
    const int tid  = threadIdx.x;
    const int lane = tid & 31;

    const unsigned listn  = g_listn[b];
    const unsigned negcnt = g_negcnt[b];
    const bool valid = (negcnt > KTOP && listn >= KTOP && listn <= CAP);

    if (tid == 0) s_sum = 0.0f;

    if (valid) {
        // ================= list-based exact top-800 =================
        const unsigned n = listn;
        const unsigned* lst = g_cand + b * CAP;
        __syncthreads();

        // level 1: hist over u>>21
        sh[tid] = 0u; sh[tid + 1024] = 0u;
        __syncthreads();
        for (unsigned q = tid; q < n; q += 1024)
            atomicAdd(&sh[lst[q] >> 21], 1u);
        __syncthreads();
        {
            const int base = 2047 - 2 * tid;
            unsigned c0 = sh[base], c1 = sh[base - 1];
            unsigned cnt = c0 + c1;
            unsigned pre = bscan1024(cnt, s_w, tid, lane);
            unsigned excl = pre - cnt;
            if (excl < KTOP && pre >= KTOP) {
                if (excl + c0 >= KTOP) { s_b1 = base;     s_k2 = KTOP - excl; }
                else                   { s_b1 = base - 1; s_k2 = KTOP - excl - c0; }
            }
        }
        __syncthreads();
        const int b1 = s_b1;
        const unsigned k2 = s_k2;

        // pass 2
        sh[tid] = 0u; sh[tid + 1024] = 0u;
        __syncthreads();
        float s = 0.0f;
        for (unsigned q = tid; q < n; q += 1024) {
            unsigned u = lst[q];
            int tb = (int)(u >> 21);
            if (tb > b1) s += softplus0(unord(u));
            else if (tb == b1) atomicAdd(&sh[(u >> 10) & 0x7FFu], 1u);
        }
#pragma unroll
        for (int o = 16; o; o >>= 1) s += __shfl_down_sync(0xffffffffu, s, o);
        if (lane == 0 && s != 0.0f) atomicAdd(&s_sum, s);
        __syncthreads();
        {
            const int base = 2047 - 2 * tid;
            unsigned c0 = sh[base], c1 = sh[base - 1];
            unsigned cnt = c0 + c1;
            unsigned pre = bscan1024(cnt, s_w, tid, lane);
            unsigned excl = pre - cnt;
            if (excl < k2 && pre >= k2) {
                if (excl + c0 >= k2) { s_b2 = base;     s_k3 = k2 - excl; }
                else                 { s_b2 = base - 1; s_k3 = k2 - excl - c0; }
            }
        }
        __syncthreads();
        const int b2 = s_b2;
        const unsigned k3 = s_k3;

        // pass 3
        sh[tid] = 0u;
        __syncthreads();
        float s2 = 0.0f;
        for (unsigned q = tid; q < n; q += 1024) {
            unsigned u = lst[q];
            if ((int)(u >> 21) != b1) continue;
            int m = (int)((u >> 10) & 0x7FFu);
            if (m > b2) s2 += softplus0(unord(u));
            else if (m == b2) atomicAdd(&sh[u & 0x3FFu], 1u);
        }
#pragma unroll
        for (int o = 16; o; o >>= 1) s2 += __shfl_down_sync(0xffffffffu, s2, o);
        if (lane == 0 && s2 != 0.0f) atomicAdd(&s_sum, s2);
        __syncthreads();

        // level 3: exact bins, closed form
        {
            const unsigned pref = ((unsigned)b1 << 21) | ((unsigned)b2 << 10);
            const int bin = 1023 - tid;
            unsigned cnt = sh[bin];
            float sp = cnt ? softplus0(unord(pref | (unsigned)bin)) : 0.0f;
            unsigned pre = bscan1024(cnt, s_w, tid, lane);
            unsigned excl = pre - cnt;
            float contrib = 0.0f;
            if (pre <= k3) contrib = (float)cnt * sp;
            else if (excl < k3) contrib = (float)(k3 - excl) * sp;
#pragma unroll
            for (int o = 16; o; o >>= 1) contrib += __shfl_down_sync(0xffffffffu, contrib, o);
            if (lane == 0 && contrib != 0.0f) atomicAdd(&s_sum, contrib);
        }
        __syncthreads();
        if (tid == 0) g_neg[b] = s_sum / (float)KTOP;
    } else {
        // ================= exact fallback (rare) =================
        if (tid < GG) {
            const float* t = tgt + (b * GG + tid) * 4;
            float gx = t[0], gy = t[1], gz = t[2], gd = t[3];
            float r2 = 0.5f * gd;
            s_gxp[tid] = gx + r2; s_gxm[tid] = gx - r2;
            s_gyp[tid] = gy + r2; s_gym[tid] = gy - r2;
            s_gzp[tid] = gz + r2; s_gzm[tid] = gz - r2;
            s_d3s[tid] = gd * gd * gd;
        }
        __syncthreads();

        const unsigned kcnt = (negcnt < KTOP) ? negcnt : KTOP;

        auto calc_u = [&](int e) -> unsigned {
            int vox = e / 3;
            int a   = e - vox * 3;
            int w = vox % 48; int t2 = vox / 48;
            int h = t2 % 48;  int d = t2 / 48;
            float cx = (float)(w * 4 + 2);
            float cy = (float)(h * 4 + 2);
            float cz = (float)(d * 4 + 2);
            float r1 = 2.5f * (float)(1 << a);
            float a3 = 125.0f * (float)(1 << (3 * a));
            float bi = -1.0f, bu = 1.0f;
#pragma unroll
            for (int g = 0; g < GG; g++) {
                float ix = fminf(cx + r1, s_gxp[g]) - fmaxf(cx - r1, s_gxm[g]); ix = fmaxf(ix, 0.0f);
                float iy = fminf(cy + r1, s_gyp[g]) - fmaxf(cy - r1, s_gym[g]); iy = fmaxf(iy, 0.0f);
                float iz = fminf(cz + r1, s_gzp[g]) - fmaxf(cz - r1, s_gzm[g]); iz = fmaxf(iz, 0.0f);
                float inter = ix * iy * iz;
                float un = a3 + s_d3s[g] - inter + 1e-6f;
                if (inter * bu > bi * un) { bi = inter; bu = un; }
            }
            if (!(bi < 0.02f * bu)) return 0u;
            float conf = pred[((size_t)b * NELEM + (size_t)e) * 5];
            return ordmap(conf);
        };

        if (negcnt <= KTOP) {
            float s = 0.0f;
            for (int e = tid; e < NELEM; e += 1024) {
                unsigned u = calc_u(e);
                if (u) s += softplus0(unord(u));
            }
#pragma unroll
            for (int o = 16; o; o >>= 1) s += __shfl_down_sync(0xffffffffu, s, o);
            if (lane == 0 && s != 0.0f) atomicAdd(&s_sum, s);
            __syncthreads();
            if (tid == 0) g_neg[b] = (kcnt > 0) ? s_sum / (float)kcnt : 0.0f;
        } else {
            // level 1
            sh[tid] = 0u; sh[tid + 1024] = 0u;
            __syncthreads();
            for (int e = tid; e < NELEM; e += 1024) {
                unsigned u = calc_u(e);
                if (u) atomicAdd(&sh[u >> 21], 1u);
            }
            __syncthreads();
            {
                const int base = 2047 - 2 * tid;
                unsigned c0 = sh[base], c1 = sh[base - 1];
                unsigned cnt = c0 + c1;
                unsigned pre = bscan1024(cnt, s_w, tid, lane);
                unsigned excl = pre - cnt;
                if (excl < KTOP && pre >= KTOP) {
                    if (excl + c0 >= KTOP) { s_b1 = base;     s_k2 = KTOP - excl; }
                    else                   { s_b1 = base - 1; s_k2 = KTOP - excl - c0; }
                }
            }
            __syncthreads();
            const int b1 = s_b1; const unsigned k2 = s_k2;
            // pass 2
            sh[tid] = 0u; sh[tid + 1024] = 0u;
            __syncthreads();
            float s = 0.0f;
            for (int e = tid; e < NELEM; e += 1024) {
                unsigned u = calc_u(e);
                if (!u) continue;
                int tb = (int)(u >> 21);
                if (tb > b1) s += softplus0(unord(u));
                else if (tb == b1) atomicAdd(&sh[(u >> 10) & 0x7FFu], 1u);
            }
#pragma unroll
            for (int o = 16; o; o >>= 1) s += __shfl_down_sync(0xffffffffu, s, o);
            if (lane == 0 && s != 0.0f) atomicAdd(&s_sum, s);
            __syncthreads();
            {
                const int base = 2047 - 2 * tid;
                unsigned c0 = sh[base], c1 = sh[base - 1];
                unsigned cnt = c0 + c1;
                unsigned pre = bscan1024(cnt, s_w, tid, lane);
                unsigned excl = pre - cnt;
                if (excl < k2 && pre >= k2) {
                    if (excl + c0 >= k2) { s_b2 = base;     s_k3 = k2 - excl; }
                    else                 { s_b2 = base - 1; s_k3 = k2 - excl - c0; }
                }
            }
            __syncthreads();
            const int b2 = s_b2; const unsigned k3 = s_k3;
            // pass 3
            sh[tid] = 0u;
            __syncthreads();
            float s2 = 0.0f;
            for (int e = tid; e < NELEM; e += 1024) {
                unsigned u = calc_u(e);
                if (!u || (int)(u >> 21) != b1) continue;
                int m = (int)((u >> 10) & 0x7FFu);
                if (m > b2) s2 += softplus0(unord(u));
                else if (m == b2) atomicAdd(&sh[u & 0x3FFu], 1u);
            }
#pragma unroll
            for (int o = 16; o; o >>= 1) s2 += __shfl_down_sync(0xffffffffu, s2, o);
            if (lane == 0 && s2 != 0.0f) atomicAdd(&s_sum, s2);
            __syncthreads();
            {
                const unsigned pref = ((unsigned)b1 << 21) | ((unsigned)b2 << 10);
                const int bin = 1023 - tid;
                unsigned cnt = sh[bin];
                float sp = cnt ? softplus0(unord(pref | (unsigned)bin)) : 0.0f;
                unsigned pre = bscan1024(cnt, s_w, tid, lane);
                unsigned excl = pre - cnt;
                float contrib = 0.0f;
                if (pre <= k3) contrib = (float)cnt * sp;
                else if (excl < k3) contrib = (float)(k3 - excl) * sp;
#pragma unroll
                for (int o = 16; o; o >>= 1) contrib += __shfl_down_sync(0xffffffffu, contrib, o);
                if (lane == 0 && contrib != 0.0f) atomicAdd(&s_sum, contrib);
            }
            __syncthreads();
            if (tid == 0) g_neg[b] = s_sum / (float)KTOP;
        }
    }

    // ---- arrive; last block finalizes + cleans ----
    __syncthreads();
    if (tid == 0) {
        fence_rel();
        s_fin = (atomicAdd(&g_arriveF, 1u) == BB - 1);
    }
    __syncthreads();
    if (s_fin && tid == 0) {
        fence_acq();
        float cls = 0.0f, reg = 0.0f, npsum = 0.0f;
        for (int bb = 0; bb < BB; bb++) {
            float np = (float)g_npos[bb];
            float pl = (np > 0.0f) ? 5.0f * g_pos_sum[bb] / np : 0.0f;
            float rl = (np > 0.0f) ? g_reg_sum[bb] / (4.0f * np) : 0.0f;
            cls += pl + g_neg[bb];
            reg += rl;
            npsum += np;
            g_pos_sum[bb] = 0.0f; g_reg_sum[bb] = 0.0f;
            g_npos[bb] = 0u; g_listn[bb] = 0u; g_negcnt[bb] = 0u;
        }
        g_arriveF = 0u;
        cls *= 0.25f;
        reg *= 0.25f;
        out[0] = cls + 0.5f * reg;
        out[1] = cls;
        out[2] = reg;
        out[3] = npsum;
    }
}

// ---------------- launcher ----------------
extern "C" void kernel_launch(void* const* d_in, const int* in_sizes, int n_in,
                              void* d_out, int out_size) {
    const float* pred = (const float*)d_in[0];   // (4,48,48,48,3,5)
    const float* tgt  = (const float*)d_in[1];   // (4,8,4)
    float* out = (float*)d_out;

    dim3 ga(APB, BB);            // 1296 x 4
    k_A<<<ga, 256>>>(pred, tgt);
    k_F<<<BB, 1024>>>(pred, tgt, out);
}